// round 8
// baseline (speedup 1.0000x reference)
#include <cuda_runtime.h>
#include <cuda_bf16.h>
#include <math_constants.h>
#include <cstdint>

// Problem dims (fixed by setup_inputs)
#define B_   64
#define C_   16
#define R_   1152
#define O_   64
#define NRT_ 36          // r-tiles
#define RPC_ 32          // r per pass-CTA

typedef unsigned long long ull;

// ---- scratch (device globals) ----
__device__ float g_Spart[(size_t)C_ * NRT_ * B_ * O_];   // 9.4 MB weighted partial sums
__device__ float g_Zpart[(size_t)C_ * NRT_ * B_];        // partial normalizers
__device__ float g_Mpart[(size_t)C_ * NRT_ * B_];        // partial maxima
__device__ float g_V[(size_t)C_ * B_ * O_];              // routing vector v
__device__ float g_m0[C_];
// X fragments, mma-spec order: [r][mw 0..3][kc 0..3][part hi/lo][lane] uint4
__device__ uint4 g_Xfrag[(size_t)R_ * 4 * 4 * 2 * 32];   // 18.9 MB

// ============================================================
// helpers
// ============================================================
__device__ __forceinline__ uint32_t smem_u32(const void* p) {
    uint32_t a;
    asm("{ .reg .u64 t; cvta.to.shared.u64 t, %1; cvt.u32.u64 %0, t; }" : "=r"(a) : "l"(p));
    return a;
}
__device__ __forceinline__ uint32_t swz(uint32_t b) { return b ^ ((b >> 3) & 0x70); }

__device__ __forceinline__ void ldsm4t(uint32_t& r0, uint32_t& r1, uint32_t& r2, uint32_t& r3,
                                       uint32_t addr) {
    asm volatile("ldmatrix.sync.aligned.m8n8.x4.trans.shared.b16 {%0,%1,%2,%3}, [%4];"
                 : "=r"(r0), "=r"(r1), "=r"(r2), "=r"(r3) : "r"(addr));
}
__device__ __forceinline__ void mma16816(float* c,
                                         uint32_t a0, uint32_t a1, uint32_t a2, uint32_t a3,
                                         uint32_t b0, uint32_t b1) {
    asm volatile(
        "mma.sync.aligned.m16n8k16.row.col.f32.bf16.bf16.f32 "
        "{%0,%1,%2,%3}, {%4,%5,%6,%7}, {%8,%9}, {%0,%1,%2,%3};"
        : "+f"(c[0]), "+f"(c[1]), "+f"(c[2]), "+f"(c[3])
        : "r"(a0), "r"(a1), "r"(a2), "r"(a3), "r"(b0), "r"(b1));
}

// ---- bf16 residual split ----
__device__ __forceinline__ void split2(float v, unsigned short& h, unsigned short& l) {
    __nv_bfloat16 hb = __float2bfloat16_rn(v);
    float res = v - __bfloat162float(hb);
    h = __bfloat16_as_ushort(hb);
    l = __bfloat16_as_ushort(__float2bfloat16_rn(res));
}
__device__ __forceinline__ uint32_t pack2(unsigned short a, unsigned short b) {
    return (uint32_t)a | ((uint32_t)b << 16);
}

// ============================================================
// KX: X -> mma-spec A fragments (hi/lo bf16). Blocks < C_ also compute m0.
// ============================================================
__global__ void __launch_bounds__(256) cap_kx(const float* __restrict__ x,
                                              const float* __restrict__ l0) {
    const int r = blockIdx.x, t = threadIdx.x;
    __shared__ float xs[64][65];

    #pragma unroll
    for (int q = 0; q < 4; ++q) {
        int j = t + q * 256;
        int b = j >> 4, i4 = j & 15;
        float4 v = *(const float4*)(x + ((size_t)b * R_ + r) * 64 + i4 * 4);
        xs[b][i4 * 4 + 0] = v.x; xs[b][i4 * 4 + 1] = v.y;
        xs[b][i4 * 4 + 2] = v.z; xs[b][i4 * 4 + 3] = v.w;
    }
    __syncthreads();

    #pragma unroll
    for (int h = 0; h < 2; ++h) {
        int pos = t + h * 256;
        int mw = pos >> 7, rest = pos & 127, kc = rest >> 5, lane = rest & 31;
        int g = lane >> 2, t4 = lane & 3;
        int b0 = mw * 16 + g, b1 = b0 + 8, k0 = kc * 16 + 2 * t4;

        unsigned short hA, lA, hB, lB;
        uint4 hi, lo;
        split2(xs[b0][k0],     hA, lA); split2(xs[b0][k0 + 1], hB, lB);
        hi.x = pack2(hA, hB); lo.x = pack2(lA, lB);
        split2(xs[b1][k0],     hA, lA); split2(xs[b1][k0 + 1], hB, lB);
        hi.y = pack2(hA, hB); lo.y = pack2(lA, lB);
        split2(xs[b0][k0 + 8], hA, lA); split2(xs[b0][k0 + 9], hB, lB);
        hi.z = pack2(hA, hB); lo.z = pack2(lA, lB);
        split2(xs[b1][k0 + 8], hA, lA); split2(xs[b1][k0 + 9], hB, lB);
        hi.w = pack2(hA, hB); lo.w = pack2(lA, lB);

        size_t base = ((((size_t)r * 4 + mw) * 4 + kc) * 2) * 32 + lane;
        g_Xfrag[base]      = hi;
        g_Xfrag[base + 32] = lo;
    }

    if (r < C_) {
        const int c = r;
        const int lane = t & 31, wrp = t >> 5;
        __shared__ float sm[8];
        float m = -CUDART_INF_F;
        for (int i = t; i < R_; i += 256) m = fmaxf(m, l0[c * R_ + i]);
        #pragma unroll
        for (int s = 16; s; s >>= 1) m = fmaxf(m, __shfl_xor_sync(0xffffffffu, m, s));
        if (lane == 0) sm[wrp] = m;
        __syncthreads();
        if (t == 0) {
            float mm = sm[0];
            #pragma unroll
            for (int q = 1; q < 8; ++q) mm = fmaxf(mm, sm[q]);
            g_m0[c] = mm;
        }
    }
}

// ============================================================
// PASS: recompute P tile via mma (3-term bf16 split), online-max softmax
// accumulation of Spart/Zpart/Mpart. No P materialization.
// CTA = (c, 32-r tile). 8 warps: 4(m) x 2(n), warp tile 16x32.
// ============================================================
template <bool USE_V>
__global__ void __launch_bounds__(256, 2) cap_pass(const float* __restrict__ w,
                                                   const float* __restrict__ l0)
{
    __shared__ char Wh[2][8192];
    __shared__ char Wl[2][8192];
    __shared__ float dbuf[2][8][16];
    __shared__ float larr[RPC_];

    const int t = threadIdx.x, lane = t & 31, wid = t >> 5;
    const int c  = blockIdx.x / NRT_;
    const int rt = blockIdx.x % NRT_;
    const int mw = wid & 3, nw = wid >> 2;
    const int m0 = 16 * mw, n0 = 32 * nw;
    const int gq = lane >> 2, t4 = lane & 3;

    const int gg = lane >> 3, rw = lane & 7;
    const int b_k_off = rw + 8 * (gg & 1);
    const int b_n_off = 8 * (gg >> 1);

    if (t < RPC_) larr[t] = l0[c * R_ + rt * RPC_ + t] - g_m0[c];

    // v slices (thread-constant rows/cols)
    float vlo[4][2], vhi[4][2];
    if (USE_V) {
        const int b_lo = m0 + gq;
        const float* pv_lo = g_V + (size_t)(c * B_ + b_lo) * O_;
        const float* pv_hi = pv_lo + (size_t)8 * O_;
        #pragma unroll
        for (int nt = 0; nt < 4; ++nt) {
            int col = n0 + 8 * nt + 2 * t4;
            vlo[nt][0] = pv_lo[col]; vlo[nt][1] = pv_lo[col + 1];
            vhi[nt][0] = pv_hi[col]; vhi[nt][1] = pv_hi[col + 1];
        }
    }

    float sacc[4][4];
    #pragma unroll
    for (int nt = 0; nt < 4; ++nt)
        #pragma unroll
        for (int i = 0; i < 4; ++i) sacc[nt][i] = 0.f;
    float zlo = 0.f, zhi = 0.f;
    float mlo = -CUDART_INF_F, mhi = -CUDART_INF_F;

    float4 pw[4];
    auto ldgW = [&](int r) {
        const float4* ws = (const float4*)(w + ((size_t)c * R_ + r) * 4096);
        #pragma unroll
        for (int q = 0; q < 4; ++q) pw[q] = ws[t + 256 * q];
    };
    auto stsW = [&](int buf) {
        #pragma unroll
        for (int q = 0; q < 4; ++q) {
            int j = t + q * 256;
            int i = j >> 4, o4 = j & 15;
            unsigned short h0, h1, h2, h3, l0b, l1b, l2b, l3b;
            split2(pw[q].x, h0, l0b); split2(pw[q].y, h1, l1b);
            split2(pw[q].z, h2, l2b); split2(pw[q].w, h3, l3b);
            ull hip = (ull)pack2(h0, h1) | ((ull)pack2(h2, h3) << 32);
            ull lop = (ull)pack2(l0b, l1b) | ((ull)pack2(l2b, l3b) << 32);
            uint32_t off = swz((unsigned)(i * 128 + 8 * o4));
            *(ull*)(Wh[buf] + off) = hip;
            *(ull*)(Wl[buf] + off) = lop;
        }
    };

    ldgW(rt * RPC_);
    stsW(0);
    __syncthreads();

    for (int rr = 0; rr < RPC_; ++rr) {
        const int r = rt * RPC_ + rr;
        const int cur = rr & 1, nxt = cur ^ 1;
        const bool more = (rr < RPC_ - 1);

        if (more) ldgW(r + 1);

        // A fragments (direct LDG, mma-spec order)
        uint4 ahf[4], alf[4];
        {
            const uint4* fb = g_Xfrag + (((size_t)r * 4 + mw) * 4) * 2 * 32 + lane;
            #pragma unroll
            for (int kc = 0; kc < 4; ++kc) {
                ahf[kc] = fb[kc * 64];
                alf[kc] = fb[kc * 64 + 32];
            }
        }

        float acc[4][4];
        #pragma unroll
        for (int nt = 0; nt < 4; ++nt)
            #pragma unroll
            for (int i = 0; i < 4; ++i) acc[nt][i] = 0.f;

        const uint32_t WhB = smem_u32(Wh[cur]);
        const uint32_t WlB = smem_u32(Wl[cur]);

        #pragma unroll
        for (int kc = 0; kc < 4; ++kc) {
            uint32_t bh[8], bl[8];
            const int krow = kc * 16 + b_k_off;
            uint32_t offA = swz((unsigned)(krow * 128 + (n0 + b_n_off) * 2));
            uint32_t offB = swz((unsigned)(krow * 128 + (n0 + 16 + b_n_off) * 2));
            ldsm4t(bh[0], bh[1], bh[2], bh[3], WhB + offA);
            ldsm4t(bh[4], bh[5], bh[6], bh[7], WhB + offB);
            ldsm4t(bl[0], bl[1], bl[2], bl[3], WlB + offA);
            ldsm4t(bl[4], bl[5], bl[6], bl[7], WlB + offB);
            #pragma unroll
            for (int nt = 0; nt < 4; ++nt) {
                mma16816(acc[nt], ahf[kc].x, ahf[kc].y, ahf[kc].z, ahf[kc].w, bh[2 * nt], bh[2 * nt + 1]);
                mma16816(acc[nt], ahf[kc].x, ahf[kc].y, ahf[kc].z, ahf[kc].w, bl[2 * nt], bl[2 * nt + 1]);
                mma16816(acc[nt], alf[kc].x, alf[kc].y, alf[kc].z, alf[kc].w, bh[2 * nt], bh[2 * nt + 1]);
            }
        }

        if (more) stsW(nxt);

        // logits for the two rows this lane owns
        float lv_lo = larr[rr], lv_hi = larr[rr];
        if (USE_V) {
            float dp_lo = 0.f, dp_hi = 0.f;
            #pragma unroll
            for (int nt = 0; nt < 4; ++nt) {
                dp_lo += acc[nt][0] * vlo[nt][0] + acc[nt][1] * vlo[nt][1];
                dp_hi += acc[nt][2] * vhi[nt][0] + acc[nt][3] * vhi[nt][1];
            }
            dp_lo += __shfl_xor_sync(0xffffffffu, dp_lo, 1);
            dp_lo += __shfl_xor_sync(0xffffffffu, dp_lo, 2);
            dp_hi += __shfl_xor_sync(0xffffffffu, dp_hi, 1);
            dp_hi += __shfl_xor_sync(0xffffffffu, dp_hi, 2);
            if (t4 == 0) {
                dbuf[cur][wid][gq]     = dp_lo;
                dbuf[cur][wid][8 + gq] = dp_hi;
            }
            __syncthreads();
            lv_lo += dbuf[cur][mw][gq]     + dbuf[cur][mw + 4][gq];
            lv_hi += dbuf[cur][mw][8 + gq] + dbuf[cur][mw + 4][8 + gq];
        }

        // online-max accumulation (flash style), per owned row
        {
            float mn_lo = fmaxf(mlo, lv_lo);
            float mn_hi = fmaxf(mhi, lv_hi);
            float corr_lo = __expf(mlo - mn_lo);
            float corr_hi = __expf(mhi - mn_hi);
            float e_lo = __expf(lv_lo - mn_lo);
            float e_hi = __expf(lv_hi - mn_hi);
            zlo = zlo * corr_lo + e_lo;
            zhi = zhi * corr_hi + e_hi;
            #pragma unroll
            for (int nt = 0; nt < 4; ++nt) {
                sacc[nt][0] = sacc[nt][0] * corr_lo + e_lo * acc[nt][0];
                sacc[nt][1] = sacc[nt][1] * corr_lo + e_lo * acc[nt][1];
                sacc[nt][2] = sacc[nt][2] * corr_hi + e_hi * acc[nt][2];
                sacc[nt][3] = sacc[nt][3] * corr_hi + e_hi * acc[nt][3];
            }
            mlo = mn_lo; mhi = mn_hi;
        }

        __syncthreads();               // W buffer handoff
    }

    // write Spart fragments + Zpart/Mpart
    const int row = m0 + gq;
    #pragma unroll
    for (int nt = 0; nt < 4; ++nt) {
        const int col = n0 + 8 * nt + 2 * t4;
        size_t base = ((size_t)(c * NRT_ + rt) * B_ + row) * O_ + col;
        *(float2*)(g_Spart + base)                  = make_float2(sacc[nt][0], sacc[nt][1]);
        *(float2*)(g_Spart + base + (size_t)8 * O_) = make_float2(sacc[nt][2], sacc[nt][3]);
    }
    if (nw == 0 && t4 == 0) {
        size_t zb = (size_t)(c * NRT_ + rt) * B_ + row;
        g_Zpart[zb]     = zlo;
        g_Zpart[zb + 8] = zhi;
        g_Mpart[zb]     = mlo;
        g_Mpart[zb + 8] = mhi;
    }
}

// ============================================================
// REDUCE: combine tiles with per-tile maxima:
//   m* = max_t M_t;  s = Σ S_t e^{M_t-m*};  Z = Σ Z_t e^{M_t-m*};  u = squash(s/Z)
// mode 0: v = u; mode 1: v += u; mode 2: out = u.
// ============================================================
__global__ void __launch_bounds__(64) cap_reduce(int mode, float* __restrict__ out) {
    const int b = blockIdx.x & 63, c = blockIdx.x >> 6;
    const int o = threadIdx.x;

    float mstar = -CUDART_INF_F;
    #pragma unroll 4
    for (int rt = 0; rt < NRT_; ++rt)
        mstar = fmaxf(mstar, g_Mpart[(size_t)(c * NRT_ + rt) * B_ + b]);

    float s = 0.f, Z = 0.f;
    #pragma unroll 4
    for (int rt = 0; rt < NRT_; ++rt) {
        float f = __expf(g_Mpart[(size_t)(c * NRT_ + rt) * B_ + b] - mstar);
        s += f * g_Spart[((size_t)(c * NRT_ + rt) * B_ + b) * O_ + o];
        Z += f * g_Zpart[(size_t)(c * NRT_ + rt) * B_ + b];
    }
    s /= Z;

    float sq = s * s;
    #pragma unroll
    for (int sh = 16; sh; sh >>= 1) sq += __shfl_xor_sync(0xffffffffu, sq, sh);
    __shared__ float sw[2];
    if ((o & 31) == 0) sw[o >> 5] = sq;
    __syncthreads();
    sq = sw[0] + sw[1];

    float scale = (sq / (1.f + sq)) * rsqrtf(sq);
    float u = scale * s;
    size_t idx = (size_t)(c * B_ + b) * O_ + o;
    if (mode == 0)      g_V[idx] = u;
    else if (mode == 1) g_V[idx] += u;
    else                out[idx] = u;
}

// ============================================================
extern "C" void kernel_launch(void* const* d_in, const int* in_sizes, int n_in,
                              void* d_out, int out_size)
{
    const float* x  = (const float*)d_in[0];   // (B, R, I)
    const float* w  = (const float*)d_in[1];   // (C, R, I, O)
    const float* l0 = (const float*)d_in[2];   // (C, 1, R, 1, 1)
    float* out = (float*)d_out;                // (C, B, 1, 1, O)

    cap_kx<<<R_, 256>>>(x, l0);

    cap_pass<false><<<C_ * NRT_, 256>>>(w, l0);   // s0 (weights e^{l0-m0})
    cap_reduce<<<C_ * B_, 64>>>(0, out);          // v = u0

    cap_pass<true><<<C_ * NRT_, 256>>>(w, l0);    // s1 (v = u0)
    cap_reduce<<<C_ * B_, 64>>>(1, out);          // v += u1

    cap_pass<true><<<C_ * NRT_, 256>>>(w, l0);    // s2 (v = u0+u1)
    cap_reduce<<<C_ * B_, 64>>>(2, out);          // out = u2
}

// round 9
// speedup vs baseline: 1.1466x; 1.1466x over previous
#include <cuda_runtime.h>
#include <cuda_bf16.h>
#include <math_constants.h>
#include <cstdint>

// Problem dims (fixed by setup_inputs)
#define B_   64
#define C_   16
#define R_   1152
#define O_   64
#define NRT_ 36          // r-tiles
#define RPC_ 32          // r per pass-CTA

typedef unsigned long long ull;

// ---- scratch (device globals) ----
__device__ float g_Spart[(size_t)C_ * NRT_ * B_ * O_];   // 9.4 MB weighted partial sums
__device__ float g_Zpart[(size_t)C_ * NRT_ * B_];        // partial normalizers
__device__ float g_Mpart[(size_t)C_ * NRT_ * B_];        // partial maxima
__device__ float g_V[(size_t)C_ * B_ * O_];              // routing vector v
__device__ float g_m0[C_];
// X fragments, mma-spec order: [r][mw 0..3][kc 0..3][part hi/lo][lane] uint4
__device__ uint4 g_Xfrag[(size_t)R_ * 4 * 4 * 2 * 32];   // 18.9 MB

// ---- dynamic smem layout (bytes) ----
#define SM_A(buf)    ((buf) * 16384)            // 2 x 16 KB A-fragment tiles
#define SM_WH(buf)   (32768 + (buf) * 8192)     // 2 x 8 KB W-hi
#define SM_WL(buf)   (49152 + (buf) * 8192)     // 2 x 8 KB W-lo
#define SM_DBUF      65536                      // 2 x 8 x 16 floats = 1 KB
#define SM_LARR      66560                      // RPC_ floats
#define SM_TOTAL     (66560 + RPC_ * 4)

// ============================================================
// helpers
// ============================================================
__device__ __forceinline__ uint32_t smem_u32(const void* p) {
    uint32_t a;
    asm("{ .reg .u64 t; cvta.to.shared.u64 t, %1; cvt.u32.u64 %0, t; }" : "=r"(a) : "l"(p));
    return a;
}
__device__ __forceinline__ uint32_t swz(uint32_t b) { return b ^ ((b >> 3) & 0x70); }

__device__ __forceinline__ void cp16(uint32_t dst, const void* src) {
    asm volatile("cp.async.cg.shared.global [%0], [%1], 16;" :: "r"(dst), "l"(src));
}
#define CP_COMMIT() asm volatile("cp.async.commit_group;" ::: "memory")
#define CP_WAIT0()  asm volatile("cp.async.wait_group 0;" ::: "memory")

__device__ __forceinline__ void ldsm4t(uint32_t& r0, uint32_t& r1, uint32_t& r2, uint32_t& r3,
                                       uint32_t addr) {
    asm volatile("ldmatrix.sync.aligned.m8n8.x4.trans.shared.b16 {%0,%1,%2,%3}, [%4];"
                 : "=r"(r0), "=r"(r1), "=r"(r2), "=r"(r3) : "r"(addr));
}
__device__ __forceinline__ void mma16816(float* c,
                                         uint32_t a0, uint32_t a1, uint32_t a2, uint32_t a3,
                                         uint32_t b0, uint32_t b1) {
    asm volatile(
        "mma.sync.aligned.m16n8k16.row.col.f32.bf16.bf16.f32 "
        "{%0,%1,%2,%3}, {%4,%5,%6,%7}, {%8,%9}, {%0,%1,%2,%3};"
        : "+f"(c[0]), "+f"(c[1]), "+f"(c[2]), "+f"(c[3])
        : "r"(a0), "r"(a1), "r"(a2), "r"(a3), "r"(b0), "r"(b1));
}

// ---- bf16 residual split ----
__device__ __forceinline__ void split2(float v, unsigned short& h, unsigned short& l) {
    __nv_bfloat16 hb = __float2bfloat16_rn(v);
    float res = v - __bfloat162float(hb);
    h = __bfloat16_as_ushort(hb);
    l = __bfloat16_as_ushort(__float2bfloat16_rn(res));
}
__device__ __forceinline__ uint32_t pack2(unsigned short a, unsigned short b) {
    return (uint32_t)a | ((uint32_t)b << 16);
}

// ============================================================
// KX: X -> mma-spec A fragments (hi/lo bf16). Blocks < C_ also compute m0.
// ============================================================
__global__ void __launch_bounds__(256) cap_kx(const float* __restrict__ x,
                                              const float* __restrict__ l0) {
    const int r = blockIdx.x, t = threadIdx.x;
    __shared__ float xs[64][65];

    #pragma unroll
    for (int q = 0; q < 4; ++q) {
        int j = t + q * 256;
        int b = j >> 4, i4 = j & 15;
        float4 v = *(const float4*)(x + ((size_t)b * R_ + r) * 64 + i4 * 4);
        xs[b][i4 * 4 + 0] = v.x; xs[b][i4 * 4 + 1] = v.y;
        xs[b][i4 * 4 + 2] = v.z; xs[b][i4 * 4 + 3] = v.w;
    }
    __syncthreads();

    #pragma unroll
    for (int h = 0; h < 2; ++h) {
        int pos = t + h * 256;
        int mw = pos >> 7, rest = pos & 127, kc = rest >> 5, lane = rest & 31;
        int g = lane >> 2, t4 = lane & 3;
        int b0 = mw * 16 + g, b1 = b0 + 8, k0 = kc * 16 + 2 * t4;

        unsigned short hA, lA, hB, lB;
        uint4 hi, lo;
        split2(xs[b0][k0],     hA, lA); split2(xs[b0][k0 + 1], hB, lB);
        hi.x = pack2(hA, hB); lo.x = pack2(lA, lB);
        split2(xs[b1][k0],     hA, lA); split2(xs[b1][k0 + 1], hB, lB);
        hi.y = pack2(hA, hB); lo.y = pack2(lA, lB);
        split2(xs[b0][k0 + 8], hA, lA); split2(xs[b0][k0 + 9], hB, lB);
        hi.z = pack2(hA, hB); lo.z = pack2(lA, lB);
        split2(xs[b1][k0 + 8], hA, lA); split2(xs[b1][k0 + 9], hB, lB);
        hi.w = pack2(hA, hB); lo.w = pack2(lA, lB);

        size_t base = ((((size_t)r * 4 + mw) * 4 + kc) * 2) * 32 + lane;
        g_Xfrag[base]      = hi;
        g_Xfrag[base + 32] = lo;
    }

    if (r < C_) {
        const int c = r;
        const int lane = t & 31, wrp = t >> 5;
        __shared__ float sm[8];
        float m = -CUDART_INF_F;
        for (int i = t; i < R_; i += 256) m = fmaxf(m, l0[c * R_ + i]);
        #pragma unroll
        for (int s = 16; s; s >>= 1) m = fmaxf(m, __shfl_xor_sync(0xffffffffu, m, s));
        if (lane == 0) sm[wrp] = m;
        __syncthreads();
        if (t == 0) {
            float mm = sm[0];
            #pragma unroll
            for (int q = 1; q < 8; ++q) mm = fmaxf(mm, sm[q]);
            g_m0[c] = mm;
        }
    }
}

// ============================================================
// PASS: recompute P tile via mma (3-term bf16 split), online-max softmax
// accumulation of Spart/Zpart/Mpart. Pipelined: cp.async A, W prefetch,
// ONE __syncthreads per r.
// ============================================================
template <bool USE_V>
__global__ void __launch_bounds__(256, 2) cap_pass(const float* __restrict__ w,
                                                   const float* __restrict__ l0)
{
    extern __shared__ char smem[];
    const uint32_t sb = smem_u32(smem);
    float* dbuf = (float*)(smem + SM_DBUF);        // [2][8][16]
    float* larr = (float*)(smem + SM_LARR);

    const int t = threadIdx.x, lane = t & 31, wid = t >> 5;
    const int c  = blockIdx.x / NRT_;
    const int rt = blockIdx.x % NRT_;
    const int mw = wid & 3, nw = wid >> 2;
    const int n0 = 32 * nw;
    const int gq = lane >> 2, t4 = lane & 3;

    const int gg = lane >> 3, rw = lane & 7;
    const int b_k_off = rw + 8 * (gg & 1);
    const int b_n_off = 8 * (gg >> 1);

    if (t < RPC_) larr[t] = l0[c * R_ + rt * RPC_ + t] - g_m0[c];

    // v slices (thread-constant rows/cols)
    float vlo[4][2], vhi[4][2];
    if (USE_V) {
        const int b_lo = 16 * mw + gq;
        const float* pv_lo = g_V + (size_t)(c * B_ + b_lo) * O_;
        const float* pv_hi = pv_lo + (size_t)8 * O_;
        #pragma unroll
        for (int nt = 0; nt < 4; ++nt) {
            int col = n0 + 8 * nt + 2 * t4;
            vlo[nt][0] = pv_lo[col]; vlo[nt][1] = pv_lo[col + 1];
            vhi[nt][0] = pv_hi[col]; vhi[nt][1] = pv_hi[col + 1];
        }
    }

    float sacc[4][4];
    #pragma unroll
    for (int nt = 0; nt < 4; ++nt)
        #pragma unroll
        for (int i = 0; i < 4; ++i) sacc[nt][i] = 0.f;
    float zlo = 0.f, zhi = 0.f;
    float mlo = -CUDART_INF_F, mhi = -CUDART_INF_F;

    float4 pw[4];
    auto cpA = [&](int buf, int r) {
        const char* src = (const char*)(g_Xfrag + (size_t)r * 1024);
        #pragma unroll
        for (int q = 0; q < 4; ++q)
            cp16(sb + SM_A(buf) + t * 16 + q * 4096, src + t * 16 + q * 4096);
        CP_COMMIT();
    };
    auto ldgW = [&](int r) {
        const float4* ws = (const float4*)(w + ((size_t)c * R_ + r) * 4096);
        #pragma unroll
        for (int q = 0; q < 4; ++q) pw[q] = ws[t + 256 * q];
    };
    auto stsW = [&](int buf) {
        #pragma unroll
        for (int q = 0; q < 4; ++q) {
            int j = t + q * 256;
            int i = j >> 4, o4 = j & 15;
            unsigned short h0, h1, h2, h3, l0b, l1b, l2b, l3b;
            split2(pw[q].x, h0, l0b); split2(pw[q].y, h1, l1b);
            split2(pw[q].z, h2, l2b); split2(pw[q].w, h3, l3b);
            ull hip = (ull)pack2(h0, h1) | ((ull)pack2(h2, h3) << 32);
            ull lop = (ull)pack2(l0b, l1b) | ((ull)pack2(l2b, l3b) << 32);
            uint32_t off = swz((unsigned)(i * 128 + 8 * o4));
            *(ull*)(smem + SM_WH(buf) + off) = hip;
            *(ull*)(smem + SM_WL(buf) + off) = lop;
        }
    };

    // prolog: stage r0
    {
        int r0 = rt * RPC_;
        cpA(0, r0);
        ldgW(r0);
        stsW(0);
        CP_WAIT0();
    }
    __syncthreads();

    for (int rr = 0; rr < RPC_; ++rr) {
        const int r = rt * RPC_ + rr;
        const int cur = rr & 1, nxt = cur ^ 1;
        const bool more = (rr < RPC_ - 1);

        if (more) {
            cpA(nxt, r + 1);          // async A for next r (overlaps MMAs)
            ldgW(r + 1);              // W LDG in flight during MMAs
        }

        float acc[4][4];
        #pragma unroll
        for (int nt = 0; nt < 4; ++nt)
            #pragma unroll
            for (int i = 0; i < 4; ++i) acc[nt][i] = 0.f;

        const uint32_t WhB = sb + SM_WH(cur);
        const uint32_t WlB = sb + SM_WL(cur);
        const char* Afrag = smem + SM_A(cur) + (mw * 4) * 2 * 512 + lane * 16;

        #pragma unroll
        for (int kc = 0; kc < 4; ++kc) {
            uint4 ahf = *(const uint4*)(Afrag + kc * 1024);
            uint4 alf = *(const uint4*)(Afrag + kc * 1024 + 512);

            uint32_t bh[8], bl[8];
            const int krow = kc * 16 + b_k_off;
            uint32_t offA = swz((unsigned)(krow * 128 + (n0 + b_n_off) * 2));
            uint32_t offB = swz((unsigned)(krow * 128 + (n0 + 16 + b_n_off) * 2));
            ldsm4t(bh[0], bh[1], bh[2], bh[3], WhB + offA);
            ldsm4t(bh[4], bh[5], bh[6], bh[7], WhB + offB);
            ldsm4t(bl[0], bl[1], bl[2], bl[3], WlB + offA);
            ldsm4t(bl[4], bl[5], bl[6], bl[7], WlB + offB);
            #pragma unroll
            for (int nt = 0; nt < 4; ++nt) {
                mma16816(acc[nt], ahf.x, ahf.y, ahf.z, ahf.w, bh[2 * nt], bh[2 * nt + 1]);
                mma16816(acc[nt], ahf.x, ahf.y, ahf.z, ahf.w, bl[2 * nt], bl[2 * nt + 1]);
                mma16816(acc[nt], alf.x, alf.y, alf.z, alf.w, bh[2 * nt], bh[2 * nt + 1]);
            }
        }

        // dot partials (before the single sync)
        if (USE_V) {
            float dp_lo = 0.f, dp_hi = 0.f;
            #pragma unroll
            for (int nt = 0; nt < 4; ++nt) {
                dp_lo += acc[nt][0] * vlo[nt][0] + acc[nt][1] * vlo[nt][1];
                dp_hi += acc[nt][2] * vhi[nt][0] + acc[nt][3] * vhi[nt][1];
            }
            dp_lo += __shfl_xor_sync(0xffffffffu, dp_lo, 1);
            dp_lo += __shfl_xor_sync(0xffffffffu, dp_lo, 2);
            dp_hi += __shfl_xor_sync(0xffffffffu, dp_hi, 1);
            dp_hi += __shfl_xor_sync(0xffffffffu, dp_hi, 2);
            if (t4 == 0) {
                dbuf[(cur * 8 + wid) * 16 + gq]     = dp_lo;
                dbuf[(cur * 8 + wid) * 16 + 8 + gq] = dp_hi;
            }
        }

        if (more) {
            stsW(nxt);                // split+store next W (nxt buffer is free)
            CP_WAIT0();               // A(nxt) landed (overlapped with MMAs)
        }
        __syncthreads();              // single barrier: dbuf + W/A handoff

        // stats update (register-only after the sync)
        {
            float lv_lo = larr[rr], lv_hi = larr[rr];
            if (USE_V) {
                lv_lo += dbuf[(cur * 8 + mw) * 16 + gq]
                       + dbuf[(cur * 8 + mw + 4) * 16 + gq];
                lv_hi += dbuf[(cur * 8 + mw) * 16 + 8 + gq]
                       + dbuf[(cur * 8 + mw + 4) * 16 + 8 + gq];
            }
            float mn_lo = fmaxf(mlo, lv_lo);
            float mn_hi = fmaxf(mhi, lv_hi);
            float corr_lo = __expf(mlo - mn_lo);
            float corr_hi = __expf(mhi - mn_hi);
            float e_lo = __expf(lv_lo - mn_lo);
            float e_hi = __expf(lv_hi - mn_hi);
            zlo = zlo * corr_lo + e_lo;
            zhi = zhi * corr_hi + e_hi;
            #pragma unroll
            for (int nt = 0; nt < 4; ++nt) {
                sacc[nt][0] = sacc[nt][0] * corr_lo + e_lo * acc[nt][0];
                sacc[nt][1] = sacc[nt][1] * corr_lo + e_lo * acc[nt][1];
                sacc[nt][2] = sacc[nt][2] * corr_hi + e_hi * acc[nt][2];
                sacc[nt][3] = sacc[nt][3] * corr_hi + e_hi * acc[nt][3];
            }
            mlo = mn_lo; mhi = mn_hi;
        }
    }

    // write Spart fragments + Zpart/Mpart
    const int row = 16 * mw + gq;
    #pragma unroll
    for (int nt = 0; nt < 4; ++nt) {
        const int col = n0 + 8 * nt + 2 * t4;
        size_t base = ((size_t)(c * NRT_ + rt) * B_ + row) * O_ + col;
        *(float2*)(g_Spart + base)                  = make_float2(sacc[nt][0], sacc[nt][1]);
        *(float2*)(g_Spart + base + (size_t)8 * O_) = make_float2(sacc[nt][2], sacc[nt][3]);
    }
    if (nw == 0 && t4 == 0) {
        size_t zb = (size_t)(c * NRT_ + rt) * B_ + row;
        g_Zpart[zb]     = zlo;
        g_Zpart[zb + 8] = zhi;
        g_Mpart[zb]     = mlo;
        g_Mpart[zb + 8] = mhi;
    }
}

// ============================================================
// REDUCE: combine tiles with per-tile maxima; u = squash(s/Z).
// mode 0: v = u; mode 1: v += u; mode 2: out = u.
// ============================================================
__global__ void __launch_bounds__(64) cap_reduce(int mode, float* __restrict__ out) {
    const int b = blockIdx.x & 63, c = blockIdx.x >> 6;
    const int o = threadIdx.x;

    float mstar = -CUDART_INF_F;
    #pragma unroll 4
    for (int rt = 0; rt < NRT_; ++rt)
        mstar = fmaxf(mstar, g_Mpart[(size_t)(c * NRT_ + rt) * B_ + b]);

    float s = 0.f, Z = 0.f;
    #pragma unroll 4
    for (int rt = 0; rt < NRT_; ++rt) {
        float f = __expf(g_Mpart[(size_t)(c * NRT_ + rt) * B_ + b] - mstar);
        s += f * g_Spart[((size_t)(c * NRT_ + rt) * B_ + b) * O_ + o];
        Z += f * g_Zpart[(size_t)(c * NRT_ + rt) * B_ + b];
    }
    s /= Z;

    float sq = s * s;
    #pragma unroll
    for (int sh = 16; sh; sh >>= 1) sq += __shfl_xor_sync(0xffffffffu, sq, sh);
    __shared__ float sw[2];
    if ((o & 31) == 0) sw[o >> 5] = sq;
    __syncthreads();
    sq = sw[0] + sw[1];

    float scale = (sq / (1.f + sq)) * rsqrtf(sq);
    float u = scale * s;
    size_t idx = (size_t)(c * B_ + b) * O_ + o;
    if (mode == 0)      g_V[idx] = u;
    else if (mode == 1) g_V[idx] += u;
    else                out[idx] = u;
}

// ============================================================
extern "C" void kernel_launch(void* const* d_in, const int* in_sizes, int n_in,
                              void* d_out, int out_size)
{
    const float* x  = (const float*)d_in[0];   // (B, R, I)
    const float* w  = (const float*)d_in[1];   // (C, R, I, O)
    const float* l0 = (const float*)d_in[2];   // (C, 1, R, 1, 1)
    float* out = (float*)d_out;                // (C, B, 1, 1, O)

    cudaFuncSetAttribute(cap_pass<false>, cudaFuncAttributeMaxDynamicSharedMemorySize, SM_TOTAL);
    cudaFuncSetAttribute(cap_pass<true>,  cudaFuncAttributeMaxDynamicSharedMemorySize, SM_TOTAL);

    cap_kx<<<R_, 256>>>(x, l0);

    cap_pass<false><<<C_ * NRT_, 256, SM_TOTAL>>>(w, l0);   // s0
    cap_reduce<<<C_ * B_, 64>>>(0, out);                    // v = u0

    cap_pass<true><<<C_ * NRT_, 256, SM_TOTAL>>>(w, l0);    // s1 (v = u0)
    cap_reduce<<<C_ * B_, 64>>>(1, out);                    // v += u1

    cap_pass<true><<<C_ * NRT_, 256, SM_TOTAL>>>(w, l0);    // s2 (v = u0+u1)
    cap_reduce<<<C_ * B_, 64>>>(2, out);                    // out = u2
}

// round 10
// speedup vs baseline: 1.1989x; 1.0456x over previous
#include <cuda_runtime.h>
#include <cuda_bf16.h>
#include <math_constants.h>
#include <cstdint>

// Problem dims (fixed by setup_inputs)
#define B_   64
#define C_   16
#define R_   1152
#define O_   64
#define NRT_ 36          // r-tiles
#define RPC_ 32          // r per pass-CTA

typedef unsigned long long ull;

// ---- scratch (device globals) ----
__device__ float g_Spart[(size_t)C_ * NRT_ * B_ * O_];   // 9.4 MB weighted partial sums
__device__ float g_Zpart[(size_t)C_ * NRT_ * B_];        // partial normalizers
__device__ float g_Mpart[(size_t)C_ * NRT_ * B_];        // partial maxima
__device__ float g_V[(size_t)C_ * B_ * O_];              // routing vector v
__device__ float g_m0[C_];
// X fragments, mma-spec order: [r][mw 0..3][kc 0..3][part hi/lo][lane] uint4
__device__ uint4 g_Xfrag[(size_t)R_ * 4 * 4 * 2 * 32];   // 18.9 MB
// Pre-split W tiles (written by pass 0): per (c,r) 16 KB = [hi 8K | lo 8K], SW128 swizzled
__device__ char g_Wsp[(size_t)C_ * R_ * 16384];          // 302 MB

// ---- dynamic smem layout (bytes) ----
#define SM_A(buf)    ((buf) * 16384)            // 2 x 16 KB A-fragment tiles
#define SM_WH(buf)   (32768 + (buf) * 8192)     // 2 x 8 KB W-hi
#define SM_WL(buf)   (49152 + (buf) * 8192)     // 2 x 8 KB W-lo
#define SM_DBUF      65536                      // 2 x 8 x 16 floats = 1 KB
#define SM_LARR      66560                      // RPC_ floats
#define SM_TOTAL     (66560 + RPC_ * 4)

// ============================================================
// helpers
// ============================================================
__device__ __forceinline__ uint32_t smem_u32(const void* p) {
    uint32_t a;
    asm("{ .reg .u64 t; cvta.to.shared.u64 t, %1; cvt.u32.u64 %0, t; }" : "=r"(a) : "l"(p));
    return a;
}
__device__ __forceinline__ uint32_t swz(uint32_t b) { return b ^ ((b >> 3) & 0x70); }

__device__ __forceinline__ void cp16(uint32_t dst, const void* src) {
    asm volatile("cp.async.cg.shared.global [%0], [%1], 16;" :: "r"(dst), "l"(src));
}
#define CP_COMMIT() asm volatile("cp.async.commit_group;" ::: "memory")
#define CP_WAIT0()  asm volatile("cp.async.wait_group 0;" ::: "memory")

__device__ __forceinline__ void ldsm4t(uint32_t& r0, uint32_t& r1, uint32_t& r2, uint32_t& r3,
                                       uint32_t addr) {
    asm volatile("ldmatrix.sync.aligned.m8n8.x4.trans.shared.b16 {%0,%1,%2,%3}, [%4];"
                 : "=r"(r0), "=r"(r1), "=r"(r2), "=r"(r3) : "r"(addr));
}
__device__ __forceinline__ void mma16816(float* c,
                                         uint32_t a0, uint32_t a1, uint32_t a2, uint32_t a3,
                                         uint32_t b0, uint32_t b1) {
    asm volatile(
        "mma.sync.aligned.m16n8k16.row.col.f32.bf16.bf16.f32 "
        "{%0,%1,%2,%3}, {%4,%5,%6,%7}, {%8,%9}, {%0,%1,%2,%3};"
        : "+f"(c[0]), "+f"(c[1]), "+f"(c[2]), "+f"(c[3])
        : "r"(a0), "r"(a1), "r"(a2), "r"(a3), "r"(b0), "r"(b1));
}

// ---- bf16 residual split ----
__device__ __forceinline__ void split2(float v, unsigned short& h, unsigned short& l) {
    __nv_bfloat16 hb = __float2bfloat16_rn(v);
    float res = v - __bfloat162float(hb);
    h = __bfloat16_as_ushort(hb);
    l = __bfloat16_as_ushort(__float2bfloat16_rn(res));
}
__device__ __forceinline__ uint32_t pack2(unsigned short a, unsigned short b) {
    return (uint32_t)a | ((uint32_t)b << 16);
}

// ============================================================
// KX: X -> mma-spec A fragments (hi/lo bf16). Blocks < C_ also compute m0.
// ============================================================
__global__ void __launch_bounds__(256) cap_kx(const float* __restrict__ x,
                                              const float* __restrict__ l0) {
    const int r = blockIdx.x, t = threadIdx.x;
    __shared__ float xs[64][65];

    #pragma unroll
    for (int q = 0; q < 4; ++q) {
        int j = t + q * 256;
        int b = j >> 4, i4 = j & 15;
        float4 v = *(const float4*)(x + ((size_t)b * R_ + r) * 64 + i4 * 4);
        xs[b][i4 * 4 + 0] = v.x; xs[b][i4 * 4 + 1] = v.y;
        xs[b][i4 * 4 + 2] = v.z; xs[b][i4 * 4 + 3] = v.w;
    }
    __syncthreads();

    #pragma unroll
    for (int h = 0; h < 2; ++h) {
        int pos = t + h * 256;
        int mw = pos >> 7, rest = pos & 127, kc = rest >> 5, lane = rest & 31;
        int g = lane >> 2, t4 = lane & 3;
        int b0 = mw * 16 + g, b1 = b0 + 8, k0 = kc * 16 + 2 * t4;

        unsigned short hA, lA, hB, lB;
        uint4 hi, lo;
        split2(xs[b0][k0],     hA, lA); split2(xs[b0][k0 + 1], hB, lB);
        hi.x = pack2(hA, hB); lo.x = pack2(lA, lB);
        split2(xs[b1][k0],     hA, lA); split2(xs[b1][k0 + 1], hB, lB);
        hi.y = pack2(hA, hB); lo.y = pack2(lA, lB);
        split2(xs[b0][k0 + 8], hA, lA); split2(xs[b0][k0 + 9], hB, lB);
        hi.z = pack2(hA, hB); lo.z = pack2(lA, lB);
        split2(xs[b1][k0 + 8], hA, lA); split2(xs[b1][k0 + 9], hB, lB);
        hi.w = pack2(hA, hB); lo.w = pack2(lA, lB);

        size_t base = ((((size_t)r * 4 + mw) * 4 + kc) * 2) * 32 + lane;
        g_Xfrag[base]      = hi;
        g_Xfrag[base + 32] = lo;
    }

    if (r < C_) {
        const int c = r;
        const int lane = t & 31, wrp = t >> 5;
        __shared__ float sm[8];
        float m = -CUDART_INF_F;
        for (int i = t; i < R_; i += 256) m = fmaxf(m, l0[c * R_ + i]);
        #pragma unroll
        for (int s = 16; s; s >>= 1) m = fmaxf(m, __shfl_xor_sync(0xffffffffu, m, s));
        if (lane == 0) sm[wrp] = m;
        __syncthreads();
        if (t == 0) {
            float mm = sm[0];
            #pragma unroll
            for (int q = 1; q < 8; ++q) mm = fmaxf(mm, sm[q]);
            g_m0[c] = mm;
        }
    }
}

// ============================================================
// PASS: recompute P tile via mma (3-term bf16 split), online-max softmax
// accumulation of Spart/Zpart/Mpart.
// MODE 0: first pass (no v); splits W from fp32 and PERSISTS the split
//         tiles to g_Wsp for later passes.
// MODE 1: uses v; ingests pre-split W via pure cp.async.
// ============================================================
template <int MODE>
__global__ void __launch_bounds__(256, 2) cap_pass(const float* __restrict__ w,
                                                   const float* __restrict__ l0)
{
    extern __shared__ char smem[];
    const uint32_t sb = smem_u32(smem);
    float* dbuf = (float*)(smem + SM_DBUF);        // [2][8][16]
    float* larr = (float*)(smem + SM_LARR);

    const int t = threadIdx.x, lane = t & 31, wid = t >> 5;
    const int c  = blockIdx.x / NRT_;
    const int rt = blockIdx.x % NRT_;
    const int mw = wid & 3, nw = wid >> 2;
    const int n0 = 32 * nw;
    const int gq = lane >> 2, t4 = lane & 3;

    const int gg = lane >> 3, rw = lane & 7;
    const int b_k_off = rw + 8 * (gg & 1);
    const int b_n_off = 8 * (gg >> 1);

    if (t < RPC_) larr[t] = l0[c * R_ + rt * RPC_ + t] - g_m0[c];

    // v slices (thread-constant rows/cols)
    float vlo[4][2], vhi[4][2];
    if (MODE == 1) {
        const int b_lo = 16 * mw + gq;
        const float* pv_lo = g_V + (size_t)(c * B_ + b_lo) * O_;
        const float* pv_hi = pv_lo + (size_t)8 * O_;
        #pragma unroll
        for (int nt = 0; nt < 4; ++nt) {
            int col = n0 + 8 * nt + 2 * t4;
            vlo[nt][0] = pv_lo[col]; vlo[nt][1] = pv_lo[col + 1];
            vhi[nt][0] = pv_hi[col]; vhi[nt][1] = pv_hi[col + 1];
        }
    }

    float sacc[4][4];
    #pragma unroll
    for (int nt = 0; nt < 4; ++nt)
        #pragma unroll
        for (int i = 0; i < 4; ++i) sacc[nt][i] = 0.f;
    float zlo = 0.f, zhi = 0.f;
    float mlo = -CUDART_INF_F, mhi = -CUDART_INF_F;

    float4 pw[4];
    auto cpA = [&](int buf, int r) {
        const char* src = (const char*)(g_Xfrag + (size_t)r * 1024);
        #pragma unroll
        for (int q = 0; q < 4; ++q)
            cp16(sb + SM_A(buf) + t * 16 + q * 4096, src + t * 16 + q * 4096);
    };
    auto cpW = [&](int buf, int r) {    // MODE 1 only
        const char* src = g_Wsp + (size_t)(c * R_ + r) * 16384;
        cp16(sb + SM_WH(buf) + t * 16,        src + t * 16);
        cp16(sb + SM_WH(buf) + t * 16 + 4096, src + t * 16 + 4096);
        cp16(sb + SM_WL(buf) + t * 16,        src + 8192 + t * 16);
        cp16(sb + SM_WL(buf) + t * 16 + 4096, src + 8192 + t * 16 + 4096);
    };
    auto ldgW = [&](int r) {            // MODE 0 only
        const float4* ws = (const float4*)(w + ((size_t)c * R_ + r) * 4096);
        #pragma unroll
        for (int q = 0; q < 4; ++q) pw[q] = ws[t + 256 * q];
    };
    auto stsW = [&](int buf, int r) {   // MODE 0 only: STS + persist STG
        char* gw = g_Wsp + (size_t)(c * R_ + r) * 16384;
        #pragma unroll
        for (int q = 0; q < 4; ++q) {
            int j = t + q * 256;
            int i = j >> 4, o4 = j & 15;
            unsigned short h0, h1, h2, h3, l0b, l1b, l2b, l3b;
            split2(pw[q].x, h0, l0b); split2(pw[q].y, h1, l1b);
            split2(pw[q].z, h2, l2b); split2(pw[q].w, h3, l3b);
            ull hip = (ull)pack2(h0, h1) | ((ull)pack2(h2, h3) << 32);
            ull lop = (ull)pack2(l0b, l1b) | ((ull)pack2(l2b, l3b) << 32);
            uint32_t off = swz((unsigned)(i * 128 + 8 * o4));
            *(ull*)(smem + SM_WH(buf) + off) = hip;
            *(ull*)(smem + SM_WL(buf) + off) = lop;
            *(ull*)(gw + off)        = hip;
            *(ull*)(gw + 8192 + off) = lop;
        }
    };

    // prolog: stage r0
    {
        int r0 = rt * RPC_;
        cpA(0, r0);
        if (MODE == 0) {
            CP_COMMIT();
            ldgW(r0);
            stsW(0, r0);
        } else {
            cpW(0, r0);
            CP_COMMIT();
        }
        CP_WAIT0();
    }
    __syncthreads();

    for (int rr = 0; rr < RPC_; ++rr) {
        const int r = rt * RPC_ + rr;
        const int cur = rr & 1, nxt = cur ^ 1;
        const bool more = (rr < RPC_ - 1);

        if (more) {
            cpA(nxt, r + 1);
            if (MODE == 1) cpW(nxt, r + 1);
            CP_COMMIT();
            if (MODE == 0) ldgW(r + 1);   // W LDG in flight during MMAs
        }

        float acc[4][4];
        #pragma unroll
        for (int nt = 0; nt < 4; ++nt)
            #pragma unroll
            for (int i = 0; i < 4; ++i) acc[nt][i] = 0.f;

        const uint32_t WhB = sb + SM_WH(cur);
        const uint32_t WlB = sb + SM_WL(cur);
        const char* Afrag = smem + SM_A(cur) + (mw * 4) * 2 * 512 + lane * 16;

        #pragma unroll
        for (int kc = 0; kc < 4; ++kc) {
            uint4 ahf = *(const uint4*)(Afrag + kc * 1024);
            uint4 alf = *(const uint4*)(Afrag + kc * 1024 + 512);

            uint32_t bh[8], bl[8];
            const int krow = kc * 16 + b_k_off;
            uint32_t offA = swz((unsigned)(krow * 128 + (n0 + b_n_off) * 2));
            uint32_t offB = swz((unsigned)(krow * 128 + (n0 + 16 + b_n_off) * 2));
            ldsm4t(bh[0], bh[1], bh[2], bh[3], WhB + offA);
            ldsm4t(bh[4], bh[5], bh[6], bh[7], WhB + offB);
            ldsm4t(bl[0], bl[1], bl[2], bl[3], WlB + offA);
            ldsm4t(bl[4], bl[5], bl[6], bl[7], WlB + offB);
            #pragma unroll
            for (int nt = 0; nt < 4; ++nt) {
                mma16816(acc[nt], ahf.x, ahf.y, ahf.z, ahf.w, bh[2 * nt], bh[2 * nt + 1]);
                mma16816(acc[nt], ahf.x, ahf.y, ahf.z, ahf.w, bl[2 * nt], bl[2 * nt + 1]);
                mma16816(acc[nt], alf.x, alf.y, alf.z, alf.w, bh[2 * nt], bh[2 * nt + 1]);
            }
        }

        // dot partials (before the single sync)
        if (MODE == 1) {
            float dp_lo = 0.f, dp_hi = 0.f;
            #pragma unroll
            for (int nt = 0; nt < 4; ++nt) {
                dp_lo += acc[nt][0] * vlo[nt][0] + acc[nt][1] * vlo[nt][1];
                dp_hi += acc[nt][2] * vhi[nt][0] + acc[nt][3] * vhi[nt][1];
            }
            dp_lo += __shfl_xor_sync(0xffffffffu, dp_lo, 1);
            dp_lo += __shfl_xor_sync(0xffffffffu, dp_lo, 2);
            dp_hi += __shfl_xor_sync(0xffffffffu, dp_hi, 1);
            dp_hi += __shfl_xor_sync(0xffffffffu, dp_hi, 2);
            if (t4 == 0) {
                dbuf[(cur * 8 + wid) * 16 + gq]     = dp_lo;
                dbuf[(cur * 8 + wid) * 16 + 8 + gq] = dp_hi;
            }
        }

        if (more) {
            if (MODE == 0) stsW(nxt, r + 1);   // split+STS+persist next W
            CP_WAIT0();                         // staged tiles landed
        }
        __syncthreads();              // single barrier: dbuf + buffer handoff

        // stats update (register-only after the sync)
        {
            float lv_lo = larr[rr], lv_hi = larr[rr];
            if (MODE == 1) {
                lv_lo += dbuf[(cur * 8 + mw) * 16 + gq]
                       + dbuf[(cur * 8 + mw + 4) * 16 + gq];
                lv_hi += dbuf[(cur * 8 + mw) * 16 + 8 + gq]
                       + dbuf[(cur * 8 + mw + 4) * 16 + 8 + gq];
            }
            float mn_lo = fmaxf(mlo, lv_lo);
            float mn_hi = fmaxf(mhi, lv_hi);
            float corr_lo = __expf(mlo - mn_lo);
            float corr_hi = __expf(mhi - mn_hi);
            float e_lo = __expf(lv_lo - mn_lo);
            float e_hi = __expf(lv_hi - mn_hi);
            zlo = zlo * corr_lo + e_lo;
            zhi = zhi * corr_hi + e_hi;
            #pragma unroll
            for (int nt = 0; nt < 4; ++nt) {
                sacc[nt][0] = sacc[nt][0] * corr_lo + e_lo * acc[nt][0];
                sacc[nt][1] = sacc[nt][1] * corr_lo + e_lo * acc[nt][1];
                sacc[nt][2] = sacc[nt][2] * corr_hi + e_hi * acc[nt][2];
                sacc[nt][3] = sacc[nt][3] * corr_hi + e_hi * acc[nt][3];
            }
            mlo = mn_lo; mhi = mn_hi;
        }
    }

    // write Spart fragments + Zpart/Mpart
    const int row = 16 * mw + gq;
    #pragma unroll
    for (int nt = 0; nt < 4; ++nt) {
        const int col = n0 + 8 * nt + 2 * t4;
        size_t base = ((size_t)(c * NRT_ + rt) * B_ + row) * O_ + col;
        *(float2*)(g_Spart + base)                  = make_float2(sacc[nt][0], sacc[nt][1]);
        *(float2*)(g_Spart + base + (size_t)8 * O_) = make_float2(sacc[nt][2], sacc[nt][3]);
    }
    if (nw == 0 && t4 == 0) {
        size_t zb = (size_t)(c * NRT_ + rt) * B_ + row;
        g_Zpart[zb]     = zlo;
        g_Zpart[zb + 8] = zhi;
        g_Mpart[zb]     = mlo;
        g_Mpart[zb + 8] = mhi;
    }
}

// ============================================================
// REDUCE: combine tiles with per-tile maxima; u = squash(s/Z).
// mode 0: v = u; mode 1: v += u; mode 2: out = u.
// ============================================================
__global__ void __launch_bounds__(64) cap_reduce(int mode, float* __restrict__ out) {
    const int b = blockIdx.x & 63, c = blockIdx.x >> 6;
    const int o = threadIdx.x;

    float mstar = -CUDART_INF_F;
    #pragma unroll 4
    for (int rt = 0; rt < NRT_; ++rt)
        mstar = fmaxf(mstar, g_Mpart[(size_t)(c * NRT_ + rt) * B_ + b]);

    float s = 0.f, Z = 0.f;
    #pragma unroll 4
    for (int rt = 0; rt < NRT_; ++rt) {
        float f = __expf(g_Mpart[(size_t)(c * NRT_ + rt) * B_ + b] - mstar);
        s += f * g_Spart[((size_t)(c * NRT_ + rt) * B_ + b) * O_ + o];
        Z += f * g_Zpart[(size_t)(c * NRT_ + rt) * B_ + b];
    }
    s /= Z;

    float sq = s * s;
    #pragma unroll
    for (int sh = 16; sh; sh >>= 1) sq += __shfl_xor_sync(0xffffffffu, sq, sh);
    __shared__ float sw[2];
    if ((o & 31) == 0) sw[o >> 5] = sq;
    __syncthreads();
    sq = sw[0] + sw[1];

    float scale = (sq / (1.f + sq)) * rsqrtf(sq);
    float u = scale * s;
    size_t idx = (size_t)(c * B_ + b) * O_ + o;
    if (mode == 0)      g_V[idx] = u;
    else if (mode == 1) g_V[idx] += u;
    else                out[idx] = u;
}

// ============================================================
extern "C" void kernel_launch(void* const* d_in, const int* in_sizes, int n_in,
                              void* d_out, int out_size)
{
    const float* x  = (const float*)d_in[0];   // (B, R, I)
    const float* w  = (const float*)d_in[1];   // (C, R, I, O)
    const float* l0 = (const float*)d_in[2];   // (C, 1, R, 1, 1)
    float* out = (float*)d_out;                // (C, B, 1, 1, O)

    cudaFuncSetAttribute(cap_pass<0>, cudaFuncAttributeMaxDynamicSharedMemorySize, SM_TOTAL);
    cudaFuncSetAttribute(cap_pass<1>, cudaFuncAttributeMaxDynamicSharedMemorySize, SM_TOTAL);

    cap_kx<<<R_, 256>>>(x, l0);

    cap_pass<0><<<C_ * NRT_, 256, SM_TOTAL>>>(w, l0);   // s0 + persist split W
    cap_reduce<<<C_ * B_, 64>>>(0, out);                // v = u0

    cap_pass<1><<<C_ * NRT_, 256, SM_TOTAL>>>(w, l0);   // s1 (v = u0)
    cap_reduce<<<C_ * B_, 64>>>(1, out);                // v += u1

    cap_pass<1><<<C_ * NRT_, 256, SM_TOTAL>>>(w, l0);   // s2 (v = u0+u1)
    cap_reduce<<<C_ * B_, 64>>>(2, out);                // out = u2
}

// round 11
// speedup vs baseline: 1.5558x; 1.2977x over previous
#include <cuda_runtime.h>
#include <cuda_bf16.h>
#include <math_constants.h>
#include <cstdint>

// Problem dims (fixed by setup_inputs)
#define B_   64
#define C_   16
#define R_   1152
#define O_   64
#define NRT_ 36          // r-tiles
#define RPC_ 32          // r per K1 CTA

typedef unsigned long long ull;

// ---- scratch (device globals) ----
__device__ float g_P[(size_t)C_ * B_ * R_ * O_];         // 302 MB priors [c][b][r][o]
__device__ float g_Spart[(size_t)C_ * NRT_ * B_ * O_];   // 9.4 MB weighted partial sums
__device__ float g_m0[C_];
__device__ float g_Z0[C_];
// X fragments, mma-spec order: [r][mw 0..3][kc 0..3][part hi/lo][lane] uint4
__device__ uint4 g_Xfrag[(size_t)R_ * 4 * 4 * 2 * 32];   // 18.9 MB

// ---- K1 dynamic smem layout (bytes) ----
#define SM_A(buf)    ((buf) * 16384)            // 2 x 16 KB A-fragment tiles
#define SM_WH(buf)   (32768 + (buf) * 8192)     // 2 x 8 KB W-hi
#define SM_WL(buf)   (49152 + (buf) * 8192)     // 2 x 8 KB W-lo
#define SM_LARR      65536                      // RPC_ floats
#define SM_K1        (65536 + RPC_ * 4)

// ============================================================
// helpers
// ============================================================
__device__ __forceinline__ uint32_t smem_u32(const void* p) {
    uint32_t a;
    asm("{ .reg .u64 t; cvta.to.shared.u64 t, %1; cvt.u32.u64 %0, t; }" : "=r"(a) : "l"(p));
    return a;
}
__device__ __forceinline__ uint32_t swz(uint32_t b) { return b ^ ((b >> 3) & 0x70); }

__device__ __forceinline__ void cp16(uint32_t dst, const void* src) {
    asm volatile("cp.async.cg.shared.global [%0], [%1], 16;" :: "r"(dst), "l"(src));
}
#define CP_COMMIT() asm volatile("cp.async.commit_group;" ::: "memory")
#define CP_WAIT0()  asm volatile("cp.async.wait_group 0;" ::: "memory")

__device__ __forceinline__ void ldsm4t(uint32_t& r0, uint32_t& r1, uint32_t& r2, uint32_t& r3,
                                       uint32_t addr) {
    asm volatile("ldmatrix.sync.aligned.m8n8.x4.trans.shared.b16 {%0,%1,%2,%3}, [%4];"
                 : "=r"(r0), "=r"(r1), "=r"(r2), "=r"(r3) : "r"(addr));
}
__device__ __forceinline__ void mma16816(float* c,
                                         uint32_t a0, uint32_t a1, uint32_t a2, uint32_t a3,
                                         uint32_t b0, uint32_t b1) {
    asm volatile(
        "mma.sync.aligned.m16n8k16.row.col.f32.bf16.bf16.f32 "
        "{%0,%1,%2,%3}, {%4,%5,%6,%7}, {%8,%9}, {%0,%1,%2,%3};"
        : "+f"(c[0]), "+f"(c[1]), "+f"(c[2]), "+f"(c[3])
        : "r"(a0), "r"(a1), "r"(a2), "r"(a3), "r"(b0), "r"(b1));
}

// ---- bf16 residual split ----
__device__ __forceinline__ void split2(float v, unsigned short& h, unsigned short& l) {
    __nv_bfloat16 hb = __float2bfloat16_rn(v);
    float res = v - __bfloat162float(hb);
    h = __bfloat16_as_ushort(hb);
    l = __bfloat16_as_ushort(__float2bfloat16_rn(res));
}
__device__ __forceinline__ uint32_t pack2(unsigned short a, unsigned short b) {
    return (uint32_t)a | ((uint32_t)b << 16);
}

// ============================================================
// KX: X -> mma-spec A fragments (hi/lo bf16). Blocks < C_ compute m0 + Z0.
// ============================================================
__global__ void __launch_bounds__(256) cap_kx(const float* __restrict__ x,
                                              const float* __restrict__ l0) {
    const int r = blockIdx.x, t = threadIdx.x;
    __shared__ float xs[64][65];

    #pragma unroll
    for (int q = 0; q < 4; ++q) {
        int j = t + q * 256;
        int b = j >> 4, i4 = j & 15;
        float4 v = *(const float4*)(x + ((size_t)b * R_ + r) * 64 + i4 * 4);
        xs[b][i4 * 4 + 0] = v.x; xs[b][i4 * 4 + 1] = v.y;
        xs[b][i4 * 4 + 2] = v.z; xs[b][i4 * 4 + 3] = v.w;
    }
    __syncthreads();

    #pragma unroll
    for (int h = 0; h < 2; ++h) {
        int pos = t + h * 256;
        int mw = pos >> 7, rest = pos & 127, kc = rest >> 5, lane = rest & 31;
        int g = lane >> 2, t4 = lane & 3;
        int b0 = mw * 16 + g, b1 = b0 + 8, k0 = kc * 16 + 2 * t4;

        unsigned short hA, lA, hB, lB;
        uint4 hi, lo;
        split2(xs[b0][k0],     hA, lA); split2(xs[b0][k0 + 1], hB, lB);
        hi.x = pack2(hA, hB); lo.x = pack2(lA, lB);
        split2(xs[b1][k0],     hA, lA); split2(xs[b1][k0 + 1], hB, lB);
        hi.y = pack2(hA, hB); lo.y = pack2(lA, lB);
        split2(xs[b0][k0 + 8], hA, lA); split2(xs[b0][k0 + 9], hB, lB);
        hi.z = pack2(hA, hB); lo.z = pack2(lA, lB);
        split2(xs[b1][k0 + 8], hA, lA); split2(xs[b1][k0 + 9], hB, lB);
        hi.w = pack2(hA, hB); lo.w = pack2(lA, lB);

        size_t base = ((((size_t)r * 4 + mw) * 4 + kc) * 2) * 32 + lane;
        g_Xfrag[base]      = hi;
        g_Xfrag[base + 32] = lo;
    }

    if (r < C_) {
        const int c = r;
        const int lane = t & 31, wrp = t >> 5;
        __shared__ float sm[8], sz[8], mbc;

        float m = -CUDART_INF_F;
        for (int i = t; i < R_; i += 256) m = fmaxf(m, l0[c * R_ + i]);
        #pragma unroll
        for (int s = 16; s; s >>= 1) m = fmaxf(m, __shfl_xor_sync(0xffffffffu, m, s));
        if (lane == 0) sm[wrp] = m;
        __syncthreads();
        if (t == 0) {
            float mm = sm[0];
            #pragma unroll
            for (int q = 1; q < 8; ++q) mm = fmaxf(mm, sm[q]);
            mbc = mm;
        }
        __syncthreads();
        m = mbc;

        float z = 0.f;
        for (int i = t; i < R_; i += 256) z += __expf(l0[c * R_ + i] - m);
        #pragma unroll
        for (int s = 16; s; s >>= 1) z += __shfl_xor_sync(0xffffffffu, z, s);
        if (lane == 0) sz[wrp] = z;
        __syncthreads();
        if (t == 0) {
            float zz = 0.f;
            #pragma unroll
            for (int q = 0; q < 8; ++q) zz += sz[q];
            g_m0[c] = m;
            g_Z0[c] = zz;
        }
    }
}

// ============================================================
// K1: priors GEMM (3-term bf16 split via mma.sync). CTA = (c, 32-r tile).
// cp.async A fragments (exact mma layout), W LDG+split+STS overlapped,
// ONE barrier per r. Stores P [c][b][r][o] + Spart weighted by e^{l0-m0}.
// ============================================================
__global__ void __launch_bounds__(256, 2) cap_k1(const float* __restrict__ w,
                                                 const float* __restrict__ l0)
{
    extern __shared__ char smem[];
    const uint32_t sb = smem_u32(smem);
    float* larr = (float*)(smem + SM_LARR);

    const int t = threadIdx.x, lane = t & 31, wid = t >> 5;
    const int c  = blockIdx.x / NRT_;
    const int rt = blockIdx.x % NRT_;
    const int mw = wid & 3, nw = wid >> 2;
    const int n0 = 32 * nw;
    const int gq = lane >> 2, t4 = lane & 3;

    const int gg = lane >> 3, rw = lane & 7;
    const int b_k_off = rw + 8 * (gg & 1);
    const int b_n_off = 8 * (gg >> 1);

    if (t < RPC_) larr[t] = l0[c * R_ + rt * RPC_ + t] - g_m0[c];

    float sacc[4][4];
    #pragma unroll
    for (int nt = 0; nt < 4; ++nt)
        #pragma unroll
        for (int i = 0; i < 4; ++i) sacc[nt][i] = 0.f;

    float4 pw[4];
    auto cpA = [&](int buf, int r) {
        const char* src = (const char*)(g_Xfrag + (size_t)r * 1024);
        #pragma unroll
        for (int q = 0; q < 4; ++q)
            cp16(sb + SM_A(buf) + t * 16 + q * 4096, src + t * 16 + q * 4096);
        CP_COMMIT();
    };
    auto ldgW = [&](int r) {
        const float4* ws = (const float4*)(w + ((size_t)c * R_ + r) * 4096);
        #pragma unroll
        for (int q = 0; q < 4; ++q) pw[q] = ws[t + 256 * q];
    };
    auto stsW = [&](int buf) {
        #pragma unroll
        for (int q = 0; q < 4; ++q) {
            int j = t + q * 256;
            int i = j >> 4, o4 = j & 15;
            unsigned short h0, h1, h2, h3, l0b, l1b, l2b, l3b;
            split2(pw[q].x, h0, l0b); split2(pw[q].y, h1, l1b);
            split2(pw[q].z, h2, l2b); split2(pw[q].w, h3, l3b);
            ull hip = (ull)pack2(h0, h1) | ((ull)pack2(h2, h3) << 32);
            ull lop = (ull)pack2(l0b, l1b) | ((ull)pack2(l2b, l3b) << 32);
            uint32_t off = swz((unsigned)(i * 128 + 8 * o4));
            *(ull*)(smem + SM_WH(buf) + off) = hip;
            *(ull*)(smem + SM_WL(buf) + off) = lop;
        }
    };

    // prolog
    {
        int r0 = rt * RPC_;
        cpA(0, r0);
        ldgW(r0);
        stsW(0);
        CP_WAIT0();
    }
    __syncthreads();

    const int row = 16 * mw + gq;

    for (int rr = 0; rr < RPC_; ++rr) {
        const int r = rt * RPC_ + rr;
        const int cur = rr & 1, nxt = cur ^ 1;
        const bool more = (rr < RPC_ - 1);

        if (more) {
            cpA(nxt, r + 1);          // async A for next r
            ldgW(r + 1);              // W LDG in flight during MMAs
        }

        float acc[4][4];
        #pragma unroll
        for (int nt = 0; nt < 4; ++nt)
            #pragma unroll
            for (int i = 0; i < 4; ++i) acc[nt][i] = 0.f;

        const uint32_t WhB = sb + SM_WH(cur);
        const uint32_t WlB = sb + SM_WL(cur);
        const char* Afrag = smem + SM_A(cur) + (mw * 4) * 2 * 512 + lane * 16;

        #pragma unroll
        for (int kc = 0; kc < 4; ++kc) {
            uint4 ahf = *(const uint4*)(Afrag + kc * 1024);
            uint4 alf = *(const uint4*)(Afrag + kc * 1024 + 512);

            uint32_t bh[8], bl[8];
            const int krow = kc * 16 + b_k_off;
            uint32_t offA = swz((unsigned)(krow * 128 + (n0 + b_n_off) * 2));
            uint32_t offB = swz((unsigned)(krow * 128 + (n0 + 16 + b_n_off) * 2));
            ldsm4t(bh[0], bh[1], bh[2], bh[3], WhB + offA);
            ldsm4t(bh[4], bh[5], bh[6], bh[7], WhB + offB);
            ldsm4t(bl[0], bl[1], bl[2], bl[3], WlB + offA);
            ldsm4t(bl[4], bl[5], bl[6], bl[7], WlB + offB);
            #pragma unroll
            for (int nt = 0; nt < 4; ++nt) {
                mma16816(acc[nt], ahf.x, ahf.y, ahf.z, ahf.w, bh[2 * nt], bh[2 * nt + 1]);
                mma16816(acc[nt], ahf.x, ahf.y, ahf.z, ahf.w, bl[2 * nt], bl[2 * nt + 1]);
                mma16816(acc[nt], alf.x, alf.y, alf.z, alf.w, bh[2 * nt], bh[2 * nt + 1]);
            }
        }

        if (more) {
            stsW(nxt);                // split+store next W (nxt buffer free by prior sync)
            CP_WAIT0();               // A(nxt) landed
        }

        // epilogue: STG P fragments + weighted Spart (registers+global only)
        {
            const float wv = __expf(larr[rr]);
            #pragma unroll
            for (int nt = 0; nt < 4; ++nt) {
                const int col = n0 + 8 * nt + 2 * t4;
                size_t off1 = ((size_t)(c * B_ + row) * R_ + r) * O_ + col;
                size_t off2 = off1 + (size_t)8 * R_ * O_;
                *(float2*)(g_P + off1) = make_float2(acc[nt][0], acc[nt][1]);
                *(float2*)(g_P + off2) = make_float2(acc[nt][2], acc[nt][3]);
                sacc[nt][0] += wv * acc[nt][0];
                sacc[nt][1] += wv * acc[nt][1];
                sacc[nt][2] += wv * acc[nt][2];
                sacc[nt][3] += wv * acc[nt][3];
            }
        }
        __syncthreads();              // single barrier: buffer handoff
    }

    // Spart fragments [c][rt][b][o]
    #pragma unroll
    for (int nt = 0; nt < 4; ++nt) {
        const int col = n0 + 8 * nt + 2 * t4;
        size_t base1 = (((size_t)c * NRT_ + rt) * B_ + row) * O_ + col;
        size_t base2 = base1 + (size_t)8 * O_;
        *(float2*)(g_Spart + base1) = make_float2(sacc[nt][0], sacc[nt][1]);
        *(float2*)(g_Spart + base2) = make_float2(sacc[nt][2], sacc[nt][3]);
    }
}

// ============================================================
// K2: routing (both iterations). CTA = (c,b). 16 streams = 8 warps x 2
// half-warps; float4 per lane over 2 rows; online-max softmax.
// ============================================================
__global__ void __launch_bounds__(256, 3) cap_k2(
    const float* __restrict__ l0,
    float* __restrict__ out)
{
    const int b = blockIdx.x & 63;
    const int c = blockIdx.x >> 6;
    const int t = threadIdx.x, lane = t & 31, w = t >> 5;
    const int half = lane >> 4, ln16 = lane & 15;
    const int stream = w * 2 + half;

    __shared__ float l0s[R_];
    __shared__ __align__(16) float sv[O_];
    __shared__ float wm[16], wz[16];
    __shared__ __align__(16) float waccs[16][O_];

    for (int i = t; i < R_; i += 256) l0s[i] = l0[c * R_ + i];

    const float Z0 = g_Z0[c];
    const float* __restrict__ P = g_P + (size_t)(c * B_ + b) * R_ * O_;

    // --- s0 from Spart ---
    if (t < 64) {
        const float* sp = g_Spart + ((size_t)c * NRT_ * B_ + b) * O_ + t;
        float s = 0.f;
        #pragma unroll 4
        for (int rt = 0; rt < NRT_; ++rt) s += sp[(size_t)rt * B_ * O_];
        sv[t] = s / Z0;
    }
    __syncthreads();

    float4 v4;
    {
        float sq = 0.f;
        #pragma unroll 8
        for (int o = 0; o < O_; ++o) { float s_ = sv[o]; sq += s_ * s_; }
        float scale = (sq / (1.f + sq)) * rsqrtf(sq);
        float4 s4 = *(const float4*)(sv + 4 * ln16);
        v4.x = scale * s4.x; v4.y = scale * s4.y;
        v4.z = scale * s4.z; v4.w = scale * s4.w;
    }
    __syncthreads();

    for (int it = 0; it < 2; ++it) {
        float m = -CUDART_INF_F, Z = 0.f;
        float4 acc = make_float4(0.f, 0.f, 0.f, 0.f);

        #pragma unroll 4
        for (int step = 0; step < 36; ++step) {
            const int r0 = step * 32 + w * 4 + half * 2;
            const float* p0 = P + (size_t)r0 * O_ + 4 * ln16;
            float4 a = *(const float4*)(p0);
            float4 bq = *(const float4*)(p0 + O_);

            float d0 = a.x * v4.x + a.y * v4.y + a.z * v4.z + a.w * v4.w;
            float d1 = bq.x * v4.x + bq.y * v4.y + bq.z * v4.z + bq.w * v4.w;
            #pragma unroll
            for (int s = 8; s; s >>= 1) {
                d0 += __shfl_xor_sync(0xffffffffu, d0, s);
                d1 += __shfl_xor_sync(0xffffffffu, d1, s);
            }
            float lv0 = l0s[r0] + d0;
            float lv1 = l0s[r0 + 1] + d1;
            float mn = fmaxf(m, fmaxf(lv0, lv1));
            float corr = __expf(m - mn);
            float e0 = __expf(lv0 - mn);
            float e1 = __expf(lv1 - mn);
            Z = Z * corr + (e0 + e1);
            acc.x = acc.x * corr + e0 * a.x + e1 * bq.x;
            acc.y = acc.y * corr + e0 * a.y + e1 * bq.y;
            acc.z = acc.z * corr + e0 * a.z + e1 * bq.z;
            acc.w = acc.w * corr + e0 * a.w + e1 * bq.w;
            m = mn;
        }

        if (ln16 == 0) { wm[stream] = m; wz[stream] = Z; }
        *(float4*)(&waccs[stream][4 * ln16]) = acc;
        __syncthreads();

        float mstar = wm[0];
        #pragma unroll
        for (int q = 1; q < 16; ++q) mstar = fmaxf(mstar, wm[q]);

        if (t < 64) {
            float sn = 0.f, Zs = 0.f;
            #pragma unroll
            for (int q = 0; q < 16; ++q) {
                float f = __expf(wm[q] - mstar);
                sn += waccs[q][t] * f;
                Zs += wz[q] * f;
            }
            sv[t] = sn / Zs;
        }
        __syncthreads();

        float sq = 0.f;
        #pragma unroll 8
        for (int o = 0; o < O_; ++o) { float s_ = sv[o]; sq += s_ * s_; }
        float scale = (sq / (1.f + sq)) * rsqrtf(sq);

        if (it == 0) {
            float4 s4 = *(const float4*)(sv + 4 * ln16);
            v4.x += scale * s4.x; v4.y += scale * s4.y;
            v4.z += scale * s4.z; v4.w += scale * s4.w;
            __syncthreads();
        } else {
            if (t < 64) out[(size_t)(c * B_ + b) * O_ + t] = scale * sv[t];
        }
    }
}

// ============================================================
extern "C" void kernel_launch(void* const* d_in, const int* in_sizes, int n_in,
                              void* d_out, int out_size)
{
    const float* x  = (const float*)d_in[0];   // (B, R, I)
    const float* w  = (const float*)d_in[1];   // (C, R, I, O)
    const float* l0 = (const float*)d_in[2];   // (C, 1, R, 1, 1)
    float* out = (float*)d_out;                // (C, B, 1, 1, O)

    cudaFuncSetAttribute(cap_k1, cudaFuncAttributeMaxDynamicSharedMemorySize, SM_K1);

    cap_kx<<<R_, 256>>>(x, l0);
    cap_k1<<<C_ * NRT_, 256, SM_K1>>>(w, l0);
    cap_k2<<<C_ * B_, 256>>>(l0, out);
}

// round 12
// speedup vs baseline: 1.6632x; 1.0690x over previous
#include <cuda_runtime.h>
#include <cuda_bf16.h>
#include <math_constants.h>
#include <cstdint>

// Problem dims (fixed by setup_inputs)
#define B_   64
#define C_   16
#define R_   1152
#define O_   64
#define NRT_ 36          // r-tiles
#define RPC_ 32          // r per K1 CTA

typedef unsigned long long ull;

// ---- scratch (device globals) ----
__device__ float g_P[(size_t)C_ * B_ * R_ * O_];         // 302 MB priors [c][b][r][o]
__device__ float g_Spart[(size_t)C_ * NRT_ * B_ * O_];   // 9.4 MB weighted partial sums
__device__ float g_m0[C_];
__device__ float g_Z0[C_];
// X fragments, mma-spec order: [r][mw 0..3][kc 0..3][part hi/lo][lane] uint4
__device__ uint4 g_Xfrag[(size_t)R_ * 4 * 4 * 2 * 32];   // 18.9 MB

// ---- K1 dynamic smem layout (bytes) ----
#define SM_A(buf)    ((buf) * 16384)            // 2 x 16 KB A-fragment tiles
#define SM_WH(buf)   (32768 + (buf) * 8192)     // 2 x 8 KB W-hi
#define SM_WL(buf)   (49152 + (buf) * 8192)     // 2 x 8 KB W-lo
#define SM_LARR      65536                      // RPC_ floats
#define SM_K1        (65536 + RPC_ * 4)

// ============================================================
// helpers
// ============================================================
__device__ __forceinline__ uint32_t smem_u32(const void* p) {
    uint32_t a;
    asm("{ .reg .u64 t; cvta.to.shared.u64 t, %1; cvt.u32.u64 %0, t; }" : "=r"(a) : "l"(p));
    return a;
}
__device__ __forceinline__ uint32_t swz(uint32_t b) { return b ^ ((b >> 3) & 0x70); }

__device__ __forceinline__ void cp16(uint32_t dst, const void* src) {
    asm volatile("cp.async.cg.shared.global [%0], [%1], 16;" :: "r"(dst), "l"(src));
}
#define CP_COMMIT() asm volatile("cp.async.commit_group;" ::: "memory")
#define CP_WAIT0()  asm volatile("cp.async.wait_group 0;" ::: "memory")

__device__ __forceinline__ void ldsm4t(uint32_t& r0, uint32_t& r1, uint32_t& r2, uint32_t& r3,
                                       uint32_t addr) {
    asm volatile("ldmatrix.sync.aligned.m8n8.x4.trans.shared.b16 {%0,%1,%2,%3}, [%4];"
                 : "=r"(r0), "=r"(r1), "=r"(r2), "=r"(r3) : "r"(addr));
}
__device__ __forceinline__ void mma16816(float* c,
                                         uint32_t a0, uint32_t a1, uint32_t a2, uint32_t a3,
                                         uint32_t b0, uint32_t b1) {
    asm volatile(
        "mma.sync.aligned.m16n8k16.row.col.f32.bf16.bf16.f32 "
        "{%0,%1,%2,%3}, {%4,%5,%6,%7}, {%8,%9}, {%0,%1,%2,%3};"
        : "+f"(c[0]), "+f"(c[1]), "+f"(c[2]), "+f"(c[3])
        : "r"(a0), "r"(a1), "r"(a2), "r"(a3), "r"(b0), "r"(b1));
}

// ---- packed bf16 residual split: 2 elements at once ----
// hi = [bf16(b):bf16(a)], lo = [bf16(b-bh):bf16(a-ah)]  (same rn rounding as scalar path)
__device__ __forceinline__ void split2x2(float a, float b, uint32_t& hi, uint32_t& lo) {
    __nv_bfloat162 h2 = __float22bfloat162_rn(make_float2(a, b));
    uint32_t h = *reinterpret_cast<uint32_t*>(&h2);
    float ah = __uint_as_float(h << 16);
    float bh = __uint_as_float(h & 0xFFFF0000u);
    __nv_bfloat162 l2 = __float22bfloat162_rn(make_float2(a - ah, b - bh));
    hi = h;
    lo = *reinterpret_cast<uint32_t*>(&l2);
}

// ============================================================
// KX: X -> mma-spec A fragments (hi/lo bf16). Blocks < C_ compute m0 + Z0.
// ============================================================
__global__ void __launch_bounds__(256) cap_kx(const float* __restrict__ x,
                                              const float* __restrict__ l0) {
    const int r = blockIdx.x, t = threadIdx.x;
    __shared__ float xs[64][65];

    #pragma unroll
    for (int q = 0; q < 4; ++q) {
        int j = t + q * 256;
        int b = j >> 4, i4 = j & 15;
        float4 v = *(const float4*)(x + ((size_t)b * R_ + r) * 64 + i4 * 4);
        xs[b][i4 * 4 + 0] = v.x; xs[b][i4 * 4 + 1] = v.y;
        xs[b][i4 * 4 + 2] = v.z; xs[b][i4 * 4 + 3] = v.w;
    }
    __syncthreads();

    #pragma unroll
    for (int h = 0; h < 2; ++h) {
        int pos = t + h * 256;
        int mw = pos >> 7, rest = pos & 127, kc = rest >> 5, lane = rest & 31;
        int g = lane >> 2, t4 = lane & 3;
        int b0 = mw * 16 + g, b1 = b0 + 8, k0 = kc * 16 + 2 * t4;

        uint4 hi, lo;
        split2x2(xs[b0][k0],     xs[b0][k0 + 1], hi.x, lo.x);
        split2x2(xs[b1][k0],     xs[b1][k0 + 1], hi.y, lo.y);
        split2x2(xs[b0][k0 + 8], xs[b0][k0 + 9], hi.z, lo.z);
        split2x2(xs[b1][k0 + 8], xs[b1][k0 + 9], hi.w, lo.w);

        size_t base = ((((size_t)r * 4 + mw) * 4 + kc) * 2) * 32 + lane;
        g_Xfrag[base]      = hi;
        g_Xfrag[base + 32] = lo;
    }

    if (r < C_) {
        const int c = r;
        const int lane = t & 31, wrp = t >> 5;
        __shared__ float sm[8], sz[8], mbc;

        float m = -CUDART_INF_F;
        for (int i = t; i < R_; i += 256) m = fmaxf(m, l0[c * R_ + i]);
        #pragma unroll
        for (int s = 16; s; s >>= 1) m = fmaxf(m, __shfl_xor_sync(0xffffffffu, m, s));
        if (lane == 0) sm[wrp] = m;
        __syncthreads();
        if (t == 0) {
            float mm = sm[0];
            #pragma unroll
            for (int q = 1; q < 8; ++q) mm = fmaxf(mm, sm[q]);
            mbc = mm;
        }
        __syncthreads();
        m = mbc;

        float z = 0.f;
        for (int i = t; i < R_; i += 256) z += __expf(l0[c * R_ + i] - m);
        #pragma unroll
        for (int s = 16; s; s >>= 1) z += __shfl_xor_sync(0xffffffffu, z, s);
        if (lane == 0) sz[wrp] = z;
        __syncthreads();
        if (t == 0) {
            float zz = 0.f;
            #pragma unroll
            for (int q = 0; q < 8; ++q) zz += sz[q];
            g_m0[c] = m;
            g_Z0[c] = zz;
        }
    }
}

// ============================================================
// K1: priors GEMM (3-term bf16 split via mma.sync). CTA = (c, 32-r tile).
// cp.async A fragments (exact mma layout), W LDG+split+STS overlapped,
// ONE barrier per r. Stores P [c][b][r][o] + Spart weighted by e^{l0-m0}.
// ============================================================
__global__ void __launch_bounds__(256, 2) cap_k1(const float* __restrict__ w,
                                                 const float* __restrict__ l0)
{
    extern __shared__ char smem[];
    const uint32_t sb = smem_u32(smem);
    float* larr = (float*)(smem + SM_LARR);

    const int t = threadIdx.x, lane = t & 31, wid = t >> 5;
    const int c  = blockIdx.x / NRT_;
    const int rt = blockIdx.x % NRT_;
    const int mw = wid & 3, nw = wid >> 2;
    const int n0 = 32 * nw;
    const int gq = lane >> 2, t4 = lane & 3;

    const int gg = lane >> 3, rw = lane & 7;
    const int b_k_off = rw + 8 * (gg & 1);
    const int b_n_off = 8 * (gg >> 1);

    if (t < RPC_) larr[t] = l0[c * R_ + rt * RPC_ + t] - g_m0[c];

    float sacc[4][4];
    #pragma unroll
    for (int nt = 0; nt < 4; ++nt)
        #pragma unroll
        for (int i = 0; i < 4; ++i) sacc[nt][i] = 0.f;

    float4 pw[4];
    auto cpA = [&](int buf, int r) {
        const char* src = (const char*)(g_Xfrag + (size_t)r * 1024);
        #pragma unroll
        for (int q = 0; q < 4; ++q)
            cp16(sb + SM_A(buf) + t * 16 + q * 4096, src + t * 16 + q * 4096);
        CP_COMMIT();
    };
    auto ldgW = [&](int r) {
        const float4* ws = (const float4*)(w + ((size_t)c * R_ + r) * 4096);
        #pragma unroll
        for (int q = 0; q < 4; ++q) pw[q] = ws[t + 256 * q];
    };
    auto stsW = [&](int buf) {
        #pragma unroll
        for (int q = 0; q < 4; ++q) {
            int j = t + q * 256;
            int i = j >> 4, o4 = j & 15;
            uint32_t h0, l0w, h1, l1w;
            split2x2(pw[q].x, pw[q].y, h0, l0w);
            split2x2(pw[q].z, pw[q].w, h1, l1w);
            ull hip = (ull)h0 | ((ull)h1 << 32);
            ull lop = (ull)l0w | ((ull)l1w << 32);
            uint32_t off = swz((unsigned)(i * 128 + 8 * o4));
            *(ull*)(smem + SM_WH(buf) + off) = hip;
            *(ull*)(smem + SM_WL(buf) + off) = lop;
        }
    };

    // prolog
    {
        int r0 = rt * RPC_;
        cpA(0, r0);
        ldgW(r0);
        stsW(0);
        CP_WAIT0();
    }
    __syncthreads();

    const int row = 16 * mw + gq;

    for (int rr = 0; rr < RPC_; ++rr) {
        const int r = rt * RPC_ + rr;
        const int cur = rr & 1, nxt = cur ^ 1;
        const bool more = (rr < RPC_ - 1);

        if (more) {
            cpA(nxt, r + 1);          // async A for next r
            ldgW(r + 1);              // W LDG in flight during MMAs
        }

        float acc[4][4];
        #pragma unroll
        for (int nt = 0; nt < 4; ++nt)
            #pragma unroll
            for (int i = 0; i < 4; ++i) acc[nt][i] = 0.f;

        const uint32_t WhB = sb + SM_WH(cur);
        const uint32_t WlB = sb + SM_WL(cur);
        const char* Afrag = smem + SM_A(cur) + (mw * 4) * 2 * 512 + lane * 16;

        #pragma unroll
        for (int kc = 0; kc < 4; ++kc) {
            uint4 ahf = *(const uint4*)(Afrag + kc * 1024);
            uint4 alf = *(const uint4*)(Afrag + kc * 1024 + 512);

            uint32_t bh[8], bl[8];
            const int krow = kc * 16 + b_k_off;
            uint32_t offA = swz((unsigned)(krow * 128 + (n0 + b_n_off) * 2));
            uint32_t offB = swz((unsigned)(krow * 128 + (n0 + 16 + b_n_off) * 2));
            ldsm4t(bh[0], bh[1], bh[2], bh[3], WhB + offA);
            ldsm4t(bh[4], bh[5], bh[6], bh[7], WhB + offB);
            ldsm4t(bl[0], bl[1], bl[2], bl[3], WlB + offA);
            ldsm4t(bl[4], bl[5], bl[6], bl[7], WlB + offB);
            #pragma unroll
            for (int nt = 0; nt < 4; ++nt) {
                mma16816(acc[nt], ahf.x, ahf.y, ahf.z, ahf.w, bh[2 * nt], bh[2 * nt + 1]);
                mma16816(acc[nt], ahf.x, ahf.y, ahf.z, ahf.w, bl[2 * nt], bl[2 * nt + 1]);
                mma16816(acc[nt], alf.x, alf.y, alf.z, alf.w, bh[2 * nt], bh[2 * nt + 1]);
            }
        }

        if (more) {
            stsW(nxt);                // split+store next W (nxt buffer free by prior sync)
            CP_WAIT0();               // A(nxt) landed
        }

        // epilogue: STG P fragments + weighted Spart (registers+global only)
        {
            const float wv = __expf(larr[rr]);
            #pragma unroll
            for (int nt = 0; nt < 4; ++nt) {
                const int col = n0 + 8 * nt + 2 * t4;
                size_t off1 = ((size_t)(c * B_ + row) * R_ + r) * O_ + col;
                size_t off2 = off1 + (size_t)8 * R_ * O_;
                *(float2*)(g_P + off1) = make_float2(acc[nt][0], acc[nt][1]);
                *(float2*)(g_P + off2) = make_float2(acc[nt][2], acc[nt][3]);
                sacc[nt][0] += wv * acc[nt][0];
                sacc[nt][1] += wv * acc[nt][1];
                sacc[nt][2] += wv * acc[nt][2];
                sacc[nt][3] += wv * acc[nt][3];
            }
        }
        __syncthreads();              // single barrier: buffer handoff
    }

    // Spart fragments [c][rt][b][o]
    #pragma unroll
    for (int nt = 0; nt < 4; ++nt) {
        const int col = n0 + 8 * nt + 2 * t4;
        size_t base1 = (((size_t)c * NRT_ + rt) * B_ + row) * O_ + col;
        size_t base2 = base1 + (size_t)8 * O_;
        *(float2*)(g_Spart + base1) = make_float2(sacc[nt][0], sacc[nt][1]);
        *(float2*)(g_Spart + base2) = make_float2(sacc[nt][2], sacc[nt][3]);
    }
}

// ============================================================
// K2: routing (both iterations). CTA = (c,b). 16 streams = 8 warps x 2
// half-warps; float4 per lane over 2 rows; online-max softmax. occ 4.
// ============================================================
__global__ void __launch_bounds__(256, 4) cap_k2(
    const float* __restrict__ l0,
    float* __restrict__ out)
{
    const int b = blockIdx.x & 63;
    const int c = blockIdx.x >> 6;
    const int t = threadIdx.x, lane = t & 31, w = t >> 5;
    const int half = lane >> 4, ln16 = lane & 15;
    const int stream = w * 2 + half;

    __shared__ float l0s[R_];
    __shared__ __align__(16) float sv[O_];
    __shared__ float wm[16], wz[16];
    __shared__ __align__(16) float waccs[16][O_];
    __shared__ float s0p[4][O_];

    for (int i = t; i < R_; i += 256) l0s[i] = l0[c * R_ + i];

    const float Z0 = g_Z0[c];
    const float* __restrict__ P = g_P + (size_t)(c * B_ + b) * R_ * O_;

    // --- s0 from Spart (all 256 threads) ---
    {
        const int o = t & 63, quarter = t >> 6;
        const float* sp = g_Spart + ((size_t)c * NRT_ * B_ + b) * O_ + o;
        float s = 0.f;
        for (int rt = quarter; rt < NRT_; rt += 4) s += sp[(size_t)rt * B_ * O_];
        s0p[quarter][o] = s;
    }
    __syncthreads();
    if (t < 64) sv[t] = (s0p[0][t] + s0p[1][t] + s0p[2][t] + s0p[3][t]) / Z0;
    __syncthreads();

    float4 v4;
    {
        float sq = 0.f;
        #pragma unroll 8
        for (int o = 0; o < O_; ++o) { float s_ = sv[o]; sq += s_ * s_; }
        float scale = (sq / (1.f + sq)) * rsqrtf(sq);
        float4 s4 = *(const float4*)(sv + 4 * ln16);
        v4.x = scale * s4.x; v4.y = scale * s4.y;
        v4.z = scale * s4.z; v4.w = scale * s4.w;
    }
    __syncthreads();

    for (int it = 0; it < 2; ++it) {
        float m = -CUDART_INF_F, Z = 0.f;
        float4 acc = make_float4(0.f, 0.f, 0.f, 0.f);

        #pragma unroll 4
        for (int step = 0; step < 36; ++step) {
            const int r0 = step * 32 + w * 4 + half * 2;
            const float* p0 = P + (size_t)r0 * O_ + 4 * ln16;
            float4 a = *(const float4*)(p0);
            float4 bq = *(const float4*)(p0 + O_);

            float d0 = a.x * v4.x + a.y * v4.y + a.z * v4.z + a.w * v4.w;
            float d1 = bq.x * v4.x + bq.y * v4.y + bq.z * v4.z + bq.w * v4.w;
            #pragma unroll
            for (int s = 8; s; s >>= 1) {
                d0 += __shfl_xor_sync(0xffffffffu, d0, s);
                d1 += __shfl_xor_sync(0xffffffffu, d1, s);
            }
            float lv0 = l0s[r0] + d0;
            float lv1 = l0s[r0 + 1] + d1;
            float mn = fmaxf(m, fmaxf(lv0, lv1));
            float corr = __expf(m - mn);
            float e0 = __expf(lv0 - mn);
            float e1 = __expf(lv1 - mn);
            Z = Z * corr + (e0 + e1);
            acc.x = acc.x * corr + e0 * a.x + e1 * bq.x;
            acc.y = acc.y * corr + e0 * a.y + e1 * bq.y;
            acc.z = acc.z * corr + e0 * a.z + e1 * bq.z;
            acc.w = acc.w * corr + e0 * a.w + e1 * bq.w;
            m = mn;
        }

        if (ln16 == 0) { wm[stream] = m; wz[stream] = Z; }
        *(float4*)(&waccs[stream][4 * ln16]) = acc;
        __syncthreads();

        float mstar = wm[0];
        #pragma unroll
        for (int q = 1; q < 16; ++q) mstar = fmaxf(mstar, wm[q]);

        if (t < 64) {
            float sn = 0.f, Zs = 0.f;
            #pragma unroll
            for (int q = 0; q < 16; ++q) {
                float f = __expf(wm[q] - mstar);
                sn += waccs[q][t] * f;
                Zs += wz[q] * f;
            }
            sv[t] = sn / Zs;
        }
        __syncthreads();

        float sq = 0.f;
        #pragma unroll 8
        for (int o = 0; o < O_; ++o) { float s_ = sv[o]; sq += s_ * s_; }
        float scale = (sq / (1.f + sq)) * rsqrtf(sq);

        if (it == 0) {
            float4 s4 = *(const float4*)(sv + 4 * ln16);
            v4.x += scale * s4.x; v4.y += scale * s4.y;
            v4.z += scale * s4.z; v4.w += scale * s4.w;
            __syncthreads();
        } else {
            if (t < 64) out[(size_t)(c * B_ + b) * O_ + t] = scale * sv[t];
        }
    }
}

// ============================================================
extern "C" void kernel_launch(void* const* d_in, const int* in_sizes, int n_in,
                              void* d_out, int out_size)
{
    const float* x  = (const float*)d_in[0];   // (B, R, I)
    const float* w  = (const float*)d_in[1];   // (C, R, I, O)
    const float* l0 = (const float*)d_in[2];   // (C, 1, R, 1, 1)
    float* out = (float*)d_out;                // (C, B, 1, 1, O)

    cudaFuncSetAttribute(cap_k1, cudaFuncAttributeMaxDynamicSharedMemorySize, SM_K1);

    cap_kx<<<R_, 256>>>(x, l0);
    cap_k1<<<C_ * NRT_, 256, SM_K1>>>(w, l0);
    cap_k2<<<C_ * B_, 256>>>(l0, out);
}

// round 13
// speedup vs baseline: 1.6908x; 1.0166x over previous
#include <cuda_runtime.h>
#include <cuda_bf16.h>
#include <math_constants.h>
#include <cstdint>

// Problem dims (fixed by setup_inputs)
#define B_   64
#define C_   16
#define R_   1152
#define O_   64
#define NRT_ 36          // r-tiles
#define RPC_ 32          // r per K1 CTA

typedef unsigned long long ull;

// ---- scratch (device globals) ----
__device__ float g_P[(size_t)C_ * B_ * R_ * O_];         // 302 MB priors [c][b][r][o]
__device__ float g_Spart[(size_t)C_ * NRT_ * B_ * O_];   // 9.4 MB weighted partial sums
__device__ float g_m0[C_];
__device__ float g_Z0[C_];
// X fragments, mma-spec order: [r][mw 0..3][kc 0..3][part hi/lo][lane] uint4
__device__ uint4 g_Xfrag[(size_t)R_ * 4 * 4 * 2 * 32];   // 18.9 MB

// ---- K1 dynamic smem layout (bytes) ----
#define SM_A(buf)    ((buf) * 16384)            // 2 x 16 KB A-fragment tiles
#define SM_WH(buf)   (32768 + (buf) * 8192)     // 2 x 8 KB W-hi
#define SM_WL(buf)   (49152 + (buf) * 8192)     // 2 x 8 KB W-lo
#define SM_LARR      65536                      // RPC_ floats
#define SM_K1        (65536 + RPC_ * 4)

// ============================================================
// helpers
// ============================================================
__device__ __forceinline__ uint32_t smem_u32(const void* p) {
    uint32_t a;
    asm("{ .reg .u64 t; cvta.to.shared.u64 t, %1; cvt.u32.u64 %0, t; }" : "=r"(a) : "l"(p));
    return a;
}
__device__ __forceinline__ uint32_t swz(uint32_t b) { return b ^ ((b >> 3) & 0x70); }

__device__ __forceinline__ void cp16(uint32_t dst, const void* src) {
    asm volatile("cp.async.cg.shared.global [%0], [%1], 16;" :: "r"(dst), "l"(src));
}
#define CP_COMMIT() asm volatile("cp.async.commit_group;" ::: "memory")
#define CP_WAIT0()  asm volatile("cp.async.wait_group 0;" ::: "memory")

__device__ __forceinline__ void ldsm4t(uint32_t& r0, uint32_t& r1, uint32_t& r2, uint32_t& r3,
                                       uint32_t addr) {
    asm volatile("ldmatrix.sync.aligned.m8n8.x4.trans.shared.b16 {%0,%1,%2,%3}, [%4];"
                 : "=r"(r0), "=r"(r1), "=r"(r2), "=r"(r3) : "r"(addr));
}
__device__ __forceinline__ void mma16816(float* c,
                                         uint32_t a0, uint32_t a1, uint32_t a2, uint32_t a3,
                                         uint32_t b0, uint32_t b1) {
    asm volatile(
        "mma.sync.aligned.m16n8k16.row.col.f32.bf16.bf16.f32 "
        "{%0,%1,%2,%3}, {%4,%5,%6,%7}, {%8,%9}, {%0,%1,%2,%3};"
        : "+f"(c[0]), "+f"(c[1]), "+f"(c[2]), "+f"(c[3])
        : "r"(a0), "r"(a1), "r"(a2), "r"(a3), "r"(b0), "r"(b1));
}

// ---- packed bf16 residual split: 2 elements at once ----
__device__ __forceinline__ void split2x2(float a, float b, uint32_t& hi, uint32_t& lo) {
    __nv_bfloat162 h2 = __float22bfloat162_rn(make_float2(a, b));
    uint32_t h = *reinterpret_cast<uint32_t*>(&h2);
    float ah = __uint_as_float(h << 16);
    float bh = __uint_as_float(h & 0xFFFF0000u);
    __nv_bfloat162 l2 = __float22bfloat162_rn(make_float2(a - ah, b - bh));
    hi = h;
    lo = *reinterpret_cast<uint32_t*>(&l2);
}

// ============================================================
// KX: X -> mma-spec A fragments (hi/lo bf16). Blocks < C_ compute m0 + Z0.
// ============================================================
__global__ void __launch_bounds__(256) cap_kx(const float* __restrict__ x,
                                              const float* __restrict__ l0) {
    const int r = blockIdx.x, t = threadIdx.x;
    __shared__ float xs[64][65];

    #pragma unroll
    for (int q = 0; q < 4; ++q) {
        int j = t + q * 256;
        int b = j >> 4, i4 = j & 15;
        float4 v = *(const float4*)(x + ((size_t)b * R_ + r) * 64 + i4 * 4);
        xs[b][i4 * 4 + 0] = v.x; xs[b][i4 * 4 + 1] = v.y;
        xs[b][i4 * 4 + 2] = v.z; xs[b][i4 * 4 + 3] = v.w;
    }
    __syncthreads();

    #pragma unroll
    for (int h = 0; h < 2; ++h) {
        int pos = t + h * 256;
        int mw = pos >> 7, rest = pos & 127, kc = rest >> 5, lane = rest & 31;
        int g = lane >> 2, t4 = lane & 3;
        int b0 = mw * 16 + g, b1 = b0 + 8, k0 = kc * 16 + 2 * t4;

        uint4 hi, lo;
        split2x2(xs[b0][k0],     xs[b0][k0 + 1], hi.x, lo.x);
        split2x2(xs[b1][k0],     xs[b1][k0 + 1], hi.y, lo.y);
        split2x2(xs[b0][k0 + 8], xs[b0][k0 + 9], hi.z, lo.z);
        split2x2(xs[b1][k0 + 8], xs[b1][k0 + 9], hi.w, lo.w);

        size_t base = ((((size_t)r * 4 + mw) * 4 + kc) * 2) * 32 + lane;
        g_Xfrag[base]      = hi;
        g_Xfrag[base + 32] = lo;
    }

    if (r < C_) {
        const int c = r;
        const int lane = t & 31, wrp = t >> 5;
        __shared__ float sm[8], sz[8], mbc;

        float m = -CUDART_INF_F;
        for (int i = t; i < R_; i += 256) m = fmaxf(m, l0[c * R_ + i]);
        #pragma unroll
        for (int s = 16; s; s >>= 1) m = fmaxf(m, __shfl_xor_sync(0xffffffffu, m, s));
        if (lane == 0) sm[wrp] = m;
        __syncthreads();
        if (t == 0) {
            float mm = sm[0];
            #pragma unroll
            for (int q = 1; q < 8; ++q) mm = fmaxf(mm, sm[q]);
            mbc = mm;
        }
        __syncthreads();
        m = mbc;

        float z = 0.f;
        for (int i = t; i < R_; i += 256) z += __expf(l0[c * R_ + i] - m);
        #pragma unroll
        for (int s = 16; s; s >>= 1) z += __shfl_xor_sync(0xffffffffu, z, s);
        if (lane == 0) sz[wrp] = z;
        __syncthreads();
        if (t == 0) {
            float zz = 0.f;
            #pragma unroll
            for (int q = 0; q < 8; ++q) zz += sz[q];
            g_m0[c] = m;
            g_Z0[c] = zz;
        }
    }
}

// ============================================================
// K1: priors GEMM (3-term bf16 split via mma.sync). CTA = (c, 32-r tile).
// cp.async A fragments (exact mma layout), W LDG+split+STS overlapped,
// ONE barrier per r. Stores P [c][b][r][o] + Spart weighted by e^{l0-m0}.
// ============================================================
__global__ void __launch_bounds__(256, 2) cap_k1(const float* __restrict__ w,
                                                 const float* __restrict__ l0)
{
    extern __shared__ char smem[];
    const uint32_t sb = smem_u32(smem);
    float* larr = (float*)(smem + SM_LARR);

    const int t = threadIdx.x, lane = t & 31, wid = t >> 5;
    const int c  = blockIdx.x / NRT_;
    const int rt = blockIdx.x % NRT_;
    const int mw = wid & 3, nw = wid >> 2;
    const int n0 = 32 * nw;
    const int gq = lane >> 2, t4 = lane & 3;

    const int gg = lane >> 3, rw = lane & 7;
    const int b_k_off = rw + 8 * (gg & 1);
    const int b_n_off = 8 * (gg >> 1);

    if (t < RPC_) larr[t] = l0[c * R_ + rt * RPC_ + t] - g_m0[c];

    float sacc[4][4];
    #pragma unroll
    for (int nt = 0; nt < 4; ++nt)
        #pragma unroll
        for (int i = 0; i < 4; ++i) sacc[nt][i] = 0.f;

    float4 pw[4];
    auto cpA = [&](int buf, int r) {
        const char* src = (const char*)(g_Xfrag + (size_t)r * 1024);
        #pragma unroll
        for (int q = 0; q < 4; ++q)
            cp16(sb + SM_A(buf) + t * 16 + q * 4096, src + t * 16 + q * 4096);
        CP_COMMIT();
    };
    auto ldgW = [&](int r) {
        const float4* ws = (const float4*)(w + ((size_t)c * R_ + r) * 4096);
        #pragma unroll
        for (int q = 0; q < 4; ++q) pw[q] = ws[t + 256 * q];
    };
    auto stsW = [&](int buf) {
        #pragma unroll
        for (int q = 0; q < 4; ++q) {
            int j = t + q * 256;
            int i = j >> 4, o4 = j & 15;
            uint32_t h0, l0w, h1, l1w;
            split2x2(pw[q].x, pw[q].y, h0, l0w);
            split2x2(pw[q].z, pw[q].w, h1, l1w);
            ull hip = (ull)h0 | ((ull)h1 << 32);
            ull lop = (ull)l0w | ((ull)l1w << 32);
            uint32_t off = swz((unsigned)(i * 128 + 8 * o4));
            *(ull*)(smem + SM_WH(buf) + off) = hip;
            *(ull*)(smem + SM_WL(buf) + off) = lop;
        }
    };

    // prolog
    {
        int r0 = rt * RPC_;
        cpA(0, r0);
        ldgW(r0);
        stsW(0);
        CP_WAIT0();
    }
    __syncthreads();

    const int row = 16 * mw + gq;

    for (int rr = 0; rr < RPC_; ++rr) {
        const int r = rt * RPC_ + rr;
        const int cur = rr & 1, nxt = cur ^ 1;
        const bool more = (rr < RPC_ - 1);

        if (more) {
            cpA(nxt, r + 1);          // async A for next r
            ldgW(r + 1);              // W LDG in flight during MMAs
        }

        float acc[4][4];
        #pragma unroll
        for (int nt = 0; nt < 4; ++nt)
            #pragma unroll
            for (int i = 0; i < 4; ++i) acc[nt][i] = 0.f;

        const uint32_t WhB = sb + SM_WH(cur);
        const uint32_t WlB = sb + SM_WL(cur);
        const char* Afrag = smem + SM_A(cur) + (mw * 4) * 2 * 512 + lane * 16;

        #pragma unroll
        for (int kc = 0; kc < 4; ++kc) {
            uint4 ahf = *(const uint4*)(Afrag + kc * 1024);
            uint4 alf = *(const uint4*)(Afrag + kc * 1024 + 512);

            uint32_t bh[8], bl[8];
            const int krow = kc * 16 + b_k_off;
            uint32_t offA = swz((unsigned)(krow * 128 + (n0 + b_n_off) * 2));
            uint32_t offB = swz((unsigned)(krow * 128 + (n0 + 16 + b_n_off) * 2));
            ldsm4t(bh[0], bh[1], bh[2], bh[3], WhB + offA);
            ldsm4t(bh[4], bh[5], bh[6], bh[7], WhB + offB);
            ldsm4t(bl[0], bl[1], bl[2], bl[3], WlB + offA);
            ldsm4t(bl[4], bl[5], bl[6], bl[7], WlB + offB);
            #pragma unroll
            for (int nt = 0; nt < 4; ++nt) {
                mma16816(acc[nt], ahf.x, ahf.y, ahf.z, ahf.w, bh[2 * nt], bh[2 * nt + 1]);
                mma16816(acc[nt], ahf.x, ahf.y, ahf.z, ahf.w, bl[2 * nt], bl[2 * nt + 1]);
                mma16816(acc[nt], alf.x, alf.y, alf.z, alf.w, bh[2 * nt], bh[2 * nt + 1]);
            }
        }

        if (more) {
            stsW(nxt);                // split+store next W (nxt buffer free by prior sync)
            CP_WAIT0();               // A(nxt) landed
        }

        // epilogue: STG P fragments + weighted Spart (registers+global only)
        {
            const float wv = __expf(larr[rr]);
            #pragma unroll
            for (int nt = 0; nt < 4; ++nt) {
                const int col = n0 + 8 * nt + 2 * t4;
                size_t off1 = ((size_t)(c * B_ + row) * R_ + r) * O_ + col;
                size_t off2 = off1 + (size_t)8 * R_ * O_;
                *(float2*)(g_P + off1) = make_float2(acc[nt][0], acc[nt][1]);
                *(float2*)(g_P + off2) = make_float2(acc[nt][2], acc[nt][3]);
                sacc[nt][0] += wv * acc[nt][0];
                sacc[nt][1] += wv * acc[nt][1];
                sacc[nt][2] += wv * acc[nt][2];
                sacc[nt][3] += wv * acc[nt][3];
            }
        }
        __syncthreads();              // single barrier: buffer handoff
    }

    // Spart fragments [c][rt][b][o]
    #pragma unroll
    for (int nt = 0; nt < 4; ++nt) {
        const int col = n0 + 8 * nt + 2 * t4;
        size_t base1 = (((size_t)c * NRT_ + rt) * B_ + row) * O_ + col;
        size_t base2 = base1 + (size_t)8 * O_;
        *(float2*)(g_Spart + base1) = make_float2(sacc[nt][0], sacc[nt][1]);
        *(float2*)(g_Spart + base2) = make_float2(sacc[nt][2], sacc[nt][3]);
    }
}

// ============================================================
// K2: routing (both iterations). CTA = (c,b). 16 streams = 8 warps x 2
// half-warps; float4 per lane over 2 rows; online-max softmax with TWO
// independent accumulator chains (even/odd steps) merged at the end. occ 4.
// ============================================================
__global__ void __launch_bounds__(256, 4) cap_k2(
    const float* __restrict__ l0,
    float* __restrict__ out)
{
    const int b = blockIdx.x & 63;
    const int c = blockIdx.x >> 6;
    const int t = threadIdx.x, lane = t & 31, w = t >> 5;
    const int half = lane >> 4, ln16 = lane & 15;
    const int stream = w * 2 + half;

    __shared__ float l0s[R_];
    __shared__ __align__(16) float sv[O_];
    __shared__ float wm[16], wz[16];
    __shared__ __align__(16) float waccs[16][O_];
    __shared__ float s0p[4][O_];

    for (int i = t; i < R_; i += 256) l0s[i] = l0[c * R_ + i];

    const float Z0 = g_Z0[c];
    const float* __restrict__ P = g_P + (size_t)(c * B_ + b) * R_ * O_;

    // --- s0 from Spart (all 256 threads) ---
    {
        const int o = t & 63, quarter = t >> 6;
        const float* sp = g_Spart + ((size_t)c * NRT_ * B_ + b) * O_ + o;
        float s = 0.f;
        for (int rt = quarter; rt < NRT_; rt += 4) s += sp[(size_t)rt * B_ * O_];
        s0p[quarter][o] = s;
    }
    __syncthreads();
    if (t < 64) sv[t] = (s0p[0][t] + s0p[1][t] + s0p[2][t] + s0p[3][t]) / Z0;
    __syncthreads();

    float4 v4;
    {
        float sq = 0.f;
        #pragma unroll 8
        for (int o = 0; o < O_; ++o) { float s_ = sv[o]; sq += s_ * s_; }
        float scale = (sq / (1.f + sq)) * rsqrtf(sq);
        float4 s4 = *(const float4*)(sv + 4 * ln16);
        v4.x = scale * s4.x; v4.y = scale * s4.y;
        v4.z = scale * s4.z; v4.w = scale * s4.w;
    }
    __syncthreads();

    for (int it = 0; it < 2; ++it) {
        // two independent online-softmax chains (A = even steps, B = odd steps)
        float mA = -CUDART_INF_F, ZA = 0.f;
        float mB = -CUDART_INF_F, ZB = 0.f;
        float4 accA = make_float4(0.f, 0.f, 0.f, 0.f);
        float4 accB = make_float4(0.f, 0.f, 0.f, 0.f);

        #pragma unroll 3
        for (int sp = 0; sp < 18; ++sp) {
            const int r0 = (2 * sp) * 32 + w * 4 + half * 2;   // chain A rows
            const int r1 = r0 + 32;                            // chain B rows
            const float* p0 = P + (size_t)r0 * O_ + 4 * ln16;
            const float* p1 = P + (size_t)r1 * O_ + 4 * ln16;
            float4 a0 = *(const float4*)(p0);
            float4 b0 = *(const float4*)(p0 + O_);
            float4 a1 = *(const float4*)(p1);
            float4 b1 = *(const float4*)(p1 + O_);

            float dA0 = a0.x * v4.x + a0.y * v4.y + a0.z * v4.z + a0.w * v4.w;
            float dA1 = b0.x * v4.x + b0.y * v4.y + b0.z * v4.z + b0.w * v4.w;
            float dB0 = a1.x * v4.x + a1.y * v4.y + a1.z * v4.z + a1.w * v4.w;
            float dB1 = b1.x * v4.x + b1.y * v4.y + b1.z * v4.z + b1.w * v4.w;
            #pragma unroll
            for (int s = 8; s; s >>= 1) {
                dA0 += __shfl_xor_sync(0xffffffffu, dA0, s);
                dA1 += __shfl_xor_sync(0xffffffffu, dA1, s);
                dB0 += __shfl_xor_sync(0xffffffffu, dB0, s);
                dB1 += __shfl_xor_sync(0xffffffffu, dB1, s);
            }
            float lvA0 = l0s[r0]     + dA0;
            float lvA1 = l0s[r0 + 1] + dA1;
            float lvB0 = l0s[r1]     + dB0;
            float lvB1 = l0s[r1 + 1] + dB1;

            // chain A update
            {
                float mn = fmaxf(mA, fmaxf(lvA0, lvA1));
                float corr = __expf(mA - mn);
                float e0 = __expf(lvA0 - mn);
                float e1 = __expf(lvA1 - mn);
                ZA = ZA * corr + (e0 + e1);
                accA.x = accA.x * corr + e0 * a0.x + e1 * b0.x;
                accA.y = accA.y * corr + e0 * a0.y + e1 * b0.y;
                accA.z = accA.z * corr + e0 * a0.z + e1 * b0.z;
                accA.w = accA.w * corr + e0 * a0.w + e1 * b0.w;
                mA = mn;
            }
            // chain B update (independent of A)
            {
                float mn = fmaxf(mB, fmaxf(lvB0, lvB1));
                float corr = __expf(mB - mn);
                float e0 = __expf(lvB0 - mn);
                float e1 = __expf(lvB1 - mn);
                ZB = ZB * corr + (e0 + e1);
                accB.x = accB.x * corr + e0 * a1.x + e1 * b1.x;
                accB.y = accB.y * corr + e0 * a1.y + e1 * b1.y;
                accB.z = accB.z * corr + e0 * a1.z + e1 * b1.z;
                accB.w = accB.w * corr + e0 * a1.w + e1 * b1.w;
                mB = mn;
            }
        }

        // merge chains
        float m = fmaxf(mA, mB);
        float fA = __expf(mA - m), fB = __expf(mB - m);
        float Z = ZA * fA + ZB * fB;
        float4 acc;
        acc.x = accA.x * fA + accB.x * fB;
        acc.y = accA.y * fA + accB.y * fB;
        acc.z = accA.z * fA + accB.z * fB;
        acc.w = accA.w * fA + accB.w * fB;

        if (ln16 == 0) { wm[stream] = m; wz[stream] = Z; }
        *(float4*)(&waccs[stream][4 * ln16]) = acc;
        __syncthreads();

        float mstar = wm[0];
        #pragma unroll
        for (int q = 1; q < 16; ++q) mstar = fmaxf(mstar, wm[q]);

        if (t < 64) {
            float sn = 0.f, Zs = 0.f;
            #pragma unroll
            for (int q = 0; q < 16; ++q) {
                float f = __expf(wm[q] - mstar);
                sn += waccs[q][t] * f;
                Zs += wz[q] * f;
            }
            sv[t] = sn / Zs;
        }
        __syncthreads();

        float sq = 0.f;
        #pragma unroll 8
        for (int o = 0; o < O_; ++o) { float s_ = sv[o]; sq += s_ * s_; }
        float scale = (sq / (1.f + sq)) * rsqrtf(sq);

        if (it == 0) {
            float4 s4 = *(const float4*)(sv + 4 * ln16);
            v4.x += scale * s4.x; v4.y += scale * s4.y;
            v4.z += scale * s4.z; v4.w += scale * s4.w;
            __syncthreads();
        } else {
            if (t < 64) out[(size_t)(c * B_ + b) * O_ + t] = scale * sv[t];
        }
    }
}

// ============================================================
extern "C" void kernel_launch(void* const* d_in, const int* in_sizes, int n_in,
                              void* d_out, int out_size)
{
    const float* x  = (const float*)d_in[0];   // (B, R, I)
    const float* w  = (const float*)d_in[1];   // (C, R, I, O)
    const float* l0 = (const float*)d_in[2];   // (C, 1, R, 1, 1)
    float* out = (float*)d_out;                // (C, B, 1, 1, O)

    cudaFuncSetAttribute(cap_k1, cudaFuncAttributeMaxDynamicSharedMemorySize, SM_K1);

    cap_kx<<<R_, 256>>>(x, l0);
    cap_k1<<<C_ * NRT_, 256, SM_K1>>>(w, l0);
    cap_k2<<<C_ * B_, 256>>>(l0, out);
}